// round 6
// baseline (speedup 1.0000x reference)
#include <cuda_runtime.h>
#include <cuda_bf16.h>
#include <cstdint>

// Problem constants (fixed by the dataset)
#define BDIM 76
#define NDIM 151
#define KNEI 10
#define HDIM 512
#define FB 5
#define FA 89
#define FAP 128                   // padded embed K
#define MN (BDIM * NDIM)          // 11476 nodes
#define LDU2 (HDIM + FB)          // 517
#define LDU1 (2 * HDIM)           // 1024
#define DEPTH 3

// ---------------- static device scratch (no allocation allowed) -------------
__device__ __align__(128) float g_CONST[MN * HDIM];
__device__ __align__(128) float g_sbond[MN * 8];       // 5 sums + cnt (pad 8)
__device__ __align__(128) float g_Wc[HDIM * 8];        // Wc[h][0..4], bc at [5]
__device__ float g_zero512[HDIM];                      // zero bias

// ping-pong feature buffers (bf16 hi/lo)
__device__ __align__(128) __nv_bfloat16 g_Ahi0[MN * HDIM], g_Alo0[MN * HDIM];
__device__ __align__(128) __nv_bfloat16 g_Ahi1[MN * HDIM], g_Alo1[MN * HDIM];
__device__ __align__(128) __nv_bfloat16 g_GGhi[MN * HDIM], g_GGlo[MN * HDIM];
__device__ __align__(128) __nv_bfloat16 g_Wahi[HDIM * HDIM], g_Walo[HDIM * HDIM];
__device__ __align__(128) __nv_bfloat16 g_Wbhi[HDIM * HDIM], g_Wblo[HDIM * HDIM];
__device__ __align__(128) __nv_bfloat16 g_Wfhi[HDIM * HDIM], g_Wflo[HDIM * HDIM];
__device__ __align__(128) __nv_bfloat16 g_Wthi[HDIM * HDIM], g_Wtlo[HDIM * HDIM];
// padded embed operands
__device__ __align__(128) __nv_bfloat16 g_Pahi[MN * FAP], g_Palo[MN * FAP];
__device__ __align__(128) __nv_bfloat16 g_PWhi[HDIM * FAP], g_PWlo[HDIM * FAP];

// ======================= PTX helpers (sm_80-safe only) ======================
__device__ __forceinline__ uint32_t smem_u32(const void* p) {
    uint32_t a;
    asm("{ .reg .u64 t; cvta.to.shared.u64 t, %1; cvt.u32.u64 %0, t; }"
        : "=r"(a) : "l"(p));
    return a;
}
__device__ __forceinline__ void cp_async16(uint32_t dst, const void* src, int sz) {
    asm volatile("cp.async.cg.shared.global [%0], [%1], 16, %2;"
                 :: "r"(dst), "l"(src), "r"(sz) : "memory");
}
__device__ __forceinline__ void ldsm_x4(uint32_t addr, uint32_t* r) {
    asm volatile("ldmatrix.sync.aligned.m8n8.x4.shared.b16 {%0,%1,%2,%3}, [%4];"
                 : "=r"(r[0]), "=r"(r[1]), "=r"(r[2]), "=r"(r[3]) : "r"(addr));
}
__device__ __forceinline__ void mma_bf16(float* c, const uint32_t* a,
                                         uint32_t b0, uint32_t b1) {
    asm volatile(
        "mma.sync.aligned.m16n8k16.row.col.f32.bf16.bf16.f32 "
        "{%0,%1,%2,%3}, {%4,%5,%6,%7}, {%8,%9}, {%0,%1,%2,%3};"
        : "+f"(c[0]), "+f"(c[1]), "+f"(c[2]), "+f"(c[3])
        : "r"(a[0]), "r"(a[1]), "r"(a[2]), "r"(a[3]), "r"(b0), "r"(b1));
}
__device__ __forceinline__ __nv_bfloat162 split_hi2(float x, float y,
                                                    __nv_bfloat162& lo2) {
    const __nv_bfloat16 hx = __float2bfloat16_rn(x);
    const __nv_bfloat16 hy = __float2bfloat16_rn(y);
    lo2 = __nv_bfloat162(__float2bfloat16_rn(x - __bfloat162float(hx)),
                         __float2bfloat16_rn(y - __bfloat162float(hy)));
    return __nv_bfloat162(hx, hy);
}

// ======================= bf16 mma.sync GEMM =================================
// C[M, 512] = sum over pairs of A_p[M,LDA](bf16) @ B_p[512,LDA](bf16)^T
// (+ add matrix [M,512] or bias [512]).  BM=BN=128, BK=64, 3-stage cp.async.
// 256 threads = 8 warps in 4(m) x 2(n); warp tile 32x64.
#define MMA_STAGES 3
#define STAGE_BYTES 32768        // A 16KB + B 16KB
#define SMEM_MMA (MMA_STAGES * STAGE_BYTES)

struct GemmArgs { const __nv_bfloat16* a[6]; const __nv_bfloat16* b[6]; };

template <int KCPP, int LDA, bool ADDM, bool SPLIT>
__global__ __launch_bounds__(256, 2)
void mma_gemm(const GemmArgs args, int npairs,
              float* __restrict__ C,
              __nv_bfloat16* __restrict__ Chi, __nv_bfloat16* __restrict__ Clo,
              const float* __restrict__ add_or_bias, int M) {
    extern __shared__ __align__(128) char smem[];
    const uint32_t sbase = smem_u32(smem);
    const int tid = threadIdx.x, wid = tid >> 5, lane = tid & 31;
    const int bm = blockIdx.y * 128, bn = blockIdx.x * 128;
    const int wm = (wid & 3) * 32;     // warp m offset in tile
    const int wn = (wid >> 2) * 64;    // warp n offset in tile

    float acc[2][8][4] = {};

    const int lrow0 = tid >> 3;        // 0..31
    const int lch = tid & 7;           // 16B chunk within 128B row
    auto load_stage = [&](int g, int s) {
        const int p = g / KCPP, kc = g % KCPP;
        const __nv_bfloat16* Ag = args.a[p];
        const __nv_bfloat16* Bg = args.b[p];
        const uint32_t sa = sbase + s * STAGE_BYTES;
        const uint32_t sb = sa + 16384;
        #pragma unroll
        for (int it = 0; it < 4; ++it) {
            const int row = lrow0 + it * 32;
            const uint32_t soff = row * 128 + ((lch ^ (row & 7)) << 4);
            const long gmr = bm + row;
            cp_async16(sa + soff, Ag + gmr * LDA + kc * 64 + lch * 8,
                       (gmr < M) ? 16 : 0);
            cp_async16(sb + soff, Bg + (long)(bn + row) * LDA + kc * 64 + lch * 8,
                       16);
        }
        asm volatile("cp.async.commit_group;" ::: "memory");
    };

    auto compute_stage = [&](int s) {
        const uint32_t sa = sbase + s * STAGE_BYTES;
        const uint32_t sb = sa + 16384;
        #pragma unroll
        for (int ks = 0; ks < 4; ++ks) {
            uint32_t ra[2][4];
            #pragma unroll
            for (int mb = 0; mb < 2; ++mb) {
                const int row = wm + mb * 16 + (lane & 15);
                const int ch = ks * 2 + (lane >> 4);
                ldsm_x4(sa + row * 128 + ((ch ^ (row & 7)) << 4), ra[mb]);
            }
            uint32_t rb[4][4];
            #pragma unroll
            for (int nb = 0; nb < 4; ++nb) {
                const int row = wn + nb * 16 + (lane & 15);
                const int ch = ks * 2 + (lane >> 4);
                ldsm_x4(sb + row * 128 + ((ch ^ (row & 7)) << 4), rb[nb]);
            }
            #pragma unroll
            for (int mb = 0; mb < 2; ++mb)
                #pragma unroll
                for (int nb = 0; nb < 4; ++nb) {
                    mma_bf16(acc[mb][nb * 2],     ra[mb], rb[nb][0], rb[nb][2]);
                    mma_bf16(acc[mb][nb * 2 + 1], ra[mb], rb[nb][1], rb[nb][3]);
                }
        }
    };

    const int NG = npairs * KCPP;
    load_stage(0, 0);
    if (NG > 1) load_stage(1, 1);
    for (int g = 0; g < NG; ++g) {
        if (g == NG - 1)
            asm volatile("cp.async.wait_group 0;" ::: "memory");
        else
            asm volatile("cp.async.wait_group 1;" ::: "memory");
        __syncthreads();
        compute_stage(g % MMA_STAGES);
        __syncthreads();
        if (g + 2 < NG) load_stage(g + 2, (g + 2) % MMA_STAGES);
    }

    // ---- epilogue ----
    #pragma unroll
    for (int mb = 0; mb < 2; ++mb)
        #pragma unroll
        for (int nb = 0; nb < 8; ++nb) {
            const int gn = bn + wn + nb * 8 + (lane & 3) * 2;
            #pragma unroll
            for (int h = 0; h < 2; ++h) {
                const int gm = bm + wm + mb * 16 + (lane >> 2) + h * 8;
                if (gm < M) {
                    float vx = acc[mb][nb][h * 2];
                    float vy = acc[mb][nb][h * 2 + 1];
                    const float* ap = ADDM
                        ? add_or_bias + (long)gm * 512 + gn
                        : add_or_bias + gn;
                    const float2 av = *(const float2*)ap;
                    vx += av.x; vy += av.y;
                    if (SPLIT) {
                        __nv_bfloat162 lo2;
                        const __nv_bfloat162 hi2 = split_hi2(vx, vy, lo2);
                        *(__nv_bfloat162*)&Chi[(long)gm * 512 + gn] = hi2;
                        *(__nv_bfloat162*)&Clo[(long)gm * 512 + gn] = lo2;
                    } else {
                        *(float2*)&C[(long)gm * 512 + gn] = make_float2(vx, vy);
                    }
                }
            }
        }
}

// ======================= small kernels ======================================
// gather-sum over masked neighbors, reading hi/lo features, writing hi/lo sum
__global__ void gather_split_kernel(const __nv_bfloat16* __restrict__ Ahi,
                                    const __nv_bfloat16* __restrict__ Alo,
                                    const int* __restrict__ aidx,
                                    const int* __restrict__ num_nbs,
                                    __nv_bfloat16* __restrict__ Ghi,
                                    __nv_bfloat16* __restrict__ Glo) {
    const int node = blockIdx.x;               // 0..MN-1
    const int base = (node / NDIM) * NDIM;     // batch row offset
    const int e0 = threadIdx.x * 4;            // 128 threads x 4 elems
    const int nn = num_nbs[node];
    float s0 = 0.f, s1 = 0.f, s2 = 0.f, s3 = 0.f;
    #pragma unroll
    for (int k = 0; k < KNEI; ++k) {
        if (k >= nn) break;
        const int idx = __ldg(&aidx[((long)node * KNEI + k) * 2]);
        const long ro = (long)(base + idx) * HDIM + e0;
        const __nv_bfloat162 h0 = *(const __nv_bfloat162*)&Ahi[ro];
        const __nv_bfloat162 h1 = *(const __nv_bfloat162*)&Ahi[ro + 2];
        const __nv_bfloat162 l0 = *(const __nv_bfloat162*)&Alo[ro];
        const __nv_bfloat162 l1 = *(const __nv_bfloat162*)&Alo[ro + 2];
        s0 += __low2float(h0)  + __low2float(l0);
        s1 += __high2float(h0) + __high2float(l0);
        s2 += __low2float(h1)  + __low2float(l1);
        s3 += __high2float(h1) + __high2float(l1);
    }
    const long wo = (long)node * HDIM + e0;
    __nv_bfloat162 lo2a, lo2b;
    const __nv_bfloat162 hi2a = split_hi2(s0, s1, lo2a);
    const __nv_bfloat162 hi2b = split_hi2(s2, s3, lo2b);
    *(__nv_bfloat162*)&Ghi[wo]     = hi2a;
    *(__nv_bfloat162*)&Ghi[wo + 2] = hi2b;
    *(__nv_bfloat162*)&Glo[wo]     = lo2a;
    *(__nv_bfloat162*)&Glo[wo + 2] = lo2b;
}

// sbond[node][f] = sum_{k<nn} input_bond[b, bidx, f];  [5] = cnt
__global__ void sbond_kernel(const float* __restrict__ input_bond,
                             const int* __restrict__ bidx,
                             const int* __restrict__ num_nbs,
                             float* __restrict__ sbond) {
    const int node = blockIdx.x * blockDim.x + threadIdx.x;
    if (node >= MN) return;
    const int base = (node / NDIM) * NDIM;
    const int nn = num_nbs[node];
    float s[FB] = {};
    for (int k = 0; k < nn; ++k) {
        const int idx = __ldg(&bidx[((long)node * KNEI + k) * 2]);
        const float* r = input_bond + (long)(base + idx) * FB;
        #pragma unroll
        for (int f = 0; f < FB; ++f) s[f] += __ldg(&r[f]);
    }
    float4 v0 = make_float4(s[0], s[1], s[2], s[3]);
    float4 v1 = make_float4(s[4], (float)nn, 0.f, 0.f);
    *(float4*)&sbond[node * 8]     = v0;
    *(float4*)&sbond[node * 8 + 4] = v1;
}

// Wc[h][f] = sum_m W_U1[h,512+m] * W_U2[m,512+f] (f<5);  Wc[h][5] = W_U1b@b_U2
__global__ void wc_kernel(const float* __restrict__ W_U1,
                          const float* __restrict__ W_U2,
                          const float* __restrict__ b_U2,
                          float* __restrict__ Wc) {
    const int h = blockIdx.x * 8 + (threadIdx.x >> 5);
    const int lane = threadIdx.x & 31;
    float acc[6] = {};
    for (int m = lane; m < HDIM; m += 32) {
        const float u = __ldg(&W_U1[(long)h * LDU1 + HDIM + m]);
        #pragma unroll
        for (int f = 0; f < FB; ++f)
            acc[f] += u * __ldg(&W_U2[(long)m * LDU2 + HDIM + f]);
        acc[5] += u * __ldg(&b_U2[m]);
    }
    #pragma unroll
    for (int f = 0; f < 6; ++f)
        #pragma unroll
        for (int o = 16; o; o >>= 1)
            acc[f] += __shfl_xor_sync(0xFFFFFFFF, acc[f], o);
    if (lane == 0) {
        #pragma unroll
        for (int f = 0; f < 6; ++f) Wc[h * 8 + f] = acc[f];
    }
}

// CONST[node][h] = sbond . Wc[h][:5] + cnt * Wc[h][5] + b_U1[h]
__global__ void const_kernel(const float* __restrict__ sbond,
                             const float* __restrict__ Wc,
                             const float* __restrict__ b_U1,
                             float* __restrict__ C) {
    const int idx = blockIdx.x * blockDim.x + threadIdx.x;  // MN*128 threads
    if (idx >= MN * 128) return;
    const int node = idx >> 7;
    const int h0 = (idx & 127) * 4;
    const float4 s0 = *(const float4*)&sbond[node * 8];
    const float4 s1 = *(const float4*)&sbond[node * 8 + 4];
    float4 out;
    float* po = &out.x;
    #pragma unroll
    for (int j = 0; j < 4; ++j) {
        const int h = h0 + j;
        const float* w = &Wc[h * 8];
        float v = __ldg(&b_U1[h]) + s1.y * __ldg(&w[5]);
        v += s0.x * __ldg(&w[0]) + s0.y * __ldg(&w[1]) + s0.z * __ldg(&w[2])
           + s0.w * __ldg(&w[3]) + s1.x * __ldg(&w[4]);
        po[j] = v;
    }
    *(float4*)&C[(long)node * HDIM + h0] = out;
}

// transpose W_U2[:, 0:512] (ld=517) -> Wt[j][m] = W_U2[m][j], emit bf16 hi/lo
__global__ void transpose_split_kernel(const float* __restrict__ W,
                                       __nv_bfloat16* __restrict__ Thi,
                                       __nv_bfloat16* __restrict__ Tlo) {
    __shared__ float t[32][33];
    const int bx = blockIdx.x * 32, by = blockIdx.y * 32;
    const int x = threadIdx.x, y = threadIdx.y;    // 32 x 8
    #pragma unroll
    for (int i = 0; i < 32; i += 8)
        t[y + i][x] = __ldg(&W[(long)(by + y + i) * LDU2 + bx + x]);
    __syncthreads();
    #pragma unroll
    for (int i = 0; i < 32; i += 8) {
        const float v = t[x][y + i];
        const __nv_bfloat16 h = __float2bfloat16_rn(v);
        const long o = (long)(bx + y + i) * HDIM + by + x;
        Thi[o] = h;
        Tlo[o] = __float2bfloat16_rn(v - __bfloat162float(h));
    }
}

// strided weight split: out[n*512 + k] = W[n*ldw + koff + k]
__global__ void split_w_kernel(const float* __restrict__ W, int ldw, int koff,
                               __nv_bfloat16* __restrict__ hi,
                               __nv_bfloat16* __restrict__ lo) {
    const int idx = blockIdx.x * blockDim.x + threadIdx.x;
    if (idx >= HDIM * HDIM) return;
    const int n = idx >> 9, k = idx & 511;
    const float v = __ldg(&W[(long)n * ldw + koff + k]);
    const __nv_bfloat16 h = __float2bfloat16_rn(v);
    hi[idx] = h;
    lo[idx] = __float2bfloat16_rn(v - __bfloat162float(h));
}

// zero-padded split: [rows, cols] fp32 -> [rows, 128] bf16 hi/lo
__global__ void split_pad_kernel(const float* __restrict__ X, int rows, int cols,
                                 __nv_bfloat16* __restrict__ hi,
                                 __nv_bfloat16* __restrict__ lo) {
    const int idx = blockIdx.x * blockDim.x + threadIdx.x;
    if (idx >= rows * FAP) return;
    const int r = idx >> 7, c = idx & 127;
    const float v = (c < cols) ? __ldg(&X[(long)r * cols + c]) : 0.f;
    const __nv_bfloat16 h = __float2bfloat16_rn(v);
    hi[idx] = h;
    lo[idx] = __float2bfloat16_rn(v - __bfloat162float(h));
}

// ======================= host ===============================================
extern "C" void kernel_launch(void* const* d_in, const int* in_sizes, int n_in,
                              void* d_out, int out_size) {
    const float* input_atom = (const float*)d_in[0];
    const float* input_bond = (const float*)d_in[1];
    const int*   atom_nei   = (const int*)d_in[2];
    const int*   bond_nei   = (const int*)d_in[3];
    const int*   num_nbs    = (const int*)d_in[4];
    const float* W_atom     = (const float*)d_in[5];
    const float* W_U2       = (const float*)d_in[6];
    const float* b_U2       = (const float*)d_in[7];
    const float* W_U1       = (const float*)d_in[8];
    const float* b_U1       = (const float*)d_in[9];
    float* out = (float*)d_out;

    float *CONSTm, *sbond, *Wc, *zero512;
    cudaGetSymbolAddress((void**)&CONSTm, g_CONST);
    cudaGetSymbolAddress((void**)&sbond, g_sbond);
    cudaGetSymbolAddress((void**)&Wc, g_Wc);
    cudaGetSymbolAddress((void**)&zero512, g_zero512);
    __nv_bfloat16 *Ahi0, *Alo0, *Ahi1, *Alo1, *GGhi, *GGlo;
    __nv_bfloat16 *Wahi, *Walo, *Wbhi, *Wblo, *Wfhi, *Wflo, *Wthi, *Wtlo;
    __nv_bfloat16 *Pahi, *Palo, *PWhi, *PWlo;
    cudaGetSymbolAddress((void**)&Ahi0, g_Ahi0); cudaGetSymbolAddress((void**)&Alo0, g_Alo0);
    cudaGetSymbolAddress((void**)&Ahi1, g_Ahi1); cudaGetSymbolAddress((void**)&Alo1, g_Alo1);
    cudaGetSymbolAddress((void**)&GGhi, g_GGhi); cudaGetSymbolAddress((void**)&GGlo, g_GGlo);
    cudaGetSymbolAddress((void**)&Wahi, g_Wahi); cudaGetSymbolAddress((void**)&Walo, g_Walo);
    cudaGetSymbolAddress((void**)&Wbhi, g_Wbhi); cudaGetSymbolAddress((void**)&Wblo, g_Wblo);
    cudaGetSymbolAddress((void**)&Wfhi, g_Wfhi); cudaGetSymbolAddress((void**)&Wflo, g_Wflo);
    cudaGetSymbolAddress((void**)&Wthi, g_Wthi); cudaGetSymbolAddress((void**)&Wtlo, g_Wtlo);
    cudaGetSymbolAddress((void**)&Pahi, g_Pahi); cudaGetSymbolAddress((void**)&Palo, g_Palo);
    cudaGetSymbolAddress((void**)&PWhi, g_PWhi); cudaGetSymbolAddress((void**)&PWlo, g_PWlo);

    cudaFuncSetAttribute((const void*)mma_gemm<8, 512, true, true>,
                         cudaFuncAttributeMaxDynamicSharedMemorySize, SMEM_MMA);
    cudaFuncSetAttribute((const void*)mma_gemm<8, 512, true, false>,
                         cudaFuncAttributeMaxDynamicSharedMemorySize, SMEM_MMA);
    cudaFuncSetAttribute((const void*)mma_gemm<8, 512, false, true>,
                         cudaFuncAttributeMaxDynamicSharedMemorySize, SMEM_MMA);
    cudaFuncSetAttribute((const void*)mma_gemm<2, 128, false, true>,
                         cudaFuncAttributeMaxDynamicSharedMemorySize, SMEM_MMA);

    const dim3 thr(256);
    const dim3 grid_main(HDIM / 128, (MN + 127) / 128);   // 4 x 90
    const dim3 grid_sq(HDIM / 128, HDIM / 128);           // 4 x 4
    const int wblocks = (HDIM * HDIM + 255) / 256;

    // 1-2. Pad+split embed operands
    split_pad_kernel<<<(MN * FAP + 255) / 256, 256>>>(input_atom, MN, FA, Pahi, Palo);
    split_pad_kernel<<<(HDIM * FAP + 255) / 256, 256>>>(W_atom, HDIM, FA, PWhi, PWlo);

    // 3-5. Bond path via rank-6 fold: sbond -> Wc -> CONST (exact fp32)
    sbond_kernel<<<(MN + 127) / 128, 128>>>(input_bond, bond_nei, num_nbs, sbond);
    wc_kernel<<<HDIM / 8, 256>>>(W_U1, W_U2, b_U2, Wc);
    const_kernel<<<(MN * 128 + 255) / 256, 256>>>(sbond, Wc, b_U1, CONSTm);

    // 6. Embed: A0(hi/lo) = input_atom @ W_atom^T  (bf16x3)  [ncu lands here]
    {
        GemmArgs p{};
        p.a[0] = Pahi; p.a[1] = Palo; p.a[2] = Pahi;
        p.b[0] = PWhi; p.b[1] = PWhi; p.b[2] = PWlo;
        mma_gemm<2, 128, false, true><<<grid_main, thr, SMEM_MMA>>>(
            p, 3, nullptr, Ahi0, Alo0, zero512, MN);
    }

    // 7-9. Weight prep
    transpose_split_kernel<<<dim3(16, 16), dim3(32, 8)>>>(W_U2, Wthi, Wtlo);
    split_w_kernel<<<wblocks, 256>>>(W_U1, LDU1, 0, Wahi, Walo);
    split_w_kernel<<<wblocks, 256>>>(W_U1, LDU1, HDIM, Wbhi, Wblo);

    // 10. Fold: Wf(hi/lo) = W_U1b @ W_U2a  (bf16x3, split epilogue)
    {
        GemmArgs p{};
        p.a[0] = Wbhi; p.a[1] = Wblo; p.a[2] = Wbhi;
        p.b[0] = Wthi; p.b[1] = Wthi; p.b[2] = Wtlo;
        mma_gemm<8, 512, false, true><<<grid_sq, thr, SMEM_MMA>>>(
            p, 3, nullptr, Wfhi, Wflo, zero512, HDIM);
    }

    // 11+. depth iterations: GG = gather(A); A' = A@W_U1a^T + GG@Wf^T + CONST
    __nv_bfloat16* srcHi = Ahi0;
    __nv_bfloat16* srcLo = Alo0;
    for (int d = 0; d < DEPTH; ++d) {
        gather_split_kernel<<<MN, 128>>>(srcHi, srcLo, atom_nei, num_nbs,
                                         GGhi, GGlo);
        GemmArgs p{};
        p.a[0] = srcHi; p.a[1] = srcLo; p.a[2] = srcHi;
        p.b[0] = Wahi;  p.b[1] = Wahi;  p.b[2] = Walo;
        p.a[3] = GGhi;  p.a[4] = GGlo;  p.a[5] = GGhi;
        p.b[3] = Wfhi;  p.b[4] = Wfhi;  p.b[5] = Wflo;
        if (d == DEPTH - 1) {
            mma_gemm<8, 512, true, false><<<grid_main, thr, SMEM_MMA>>>(
                p, 6, out, nullptr, nullptr, CONSTm, MN);
        } else {
            __nv_bfloat16* dstHi = (srcHi == Ahi0) ? Ahi1 : Ahi0;
            __nv_bfloat16* dstLo = (srcLo == Alo0) ? Alo1 : Alo0;
            mma_gemm<8, 512, true, true><<<grid_main, thr, SMEM_MMA>>>(
                p, 6, nullptr, dstHi, dstLo, CONSTm, MN);
            srcHi = dstHi; srcLo = dstLo;
        }
    }
}

// round 7
// speedup vs baseline: 1.3303x; 1.3303x over previous
#include <cuda_runtime.h>
#include <cuda_bf16.h>
#include <cstdint>

// Problem constants (fixed by the dataset)
#define BDIM 76
#define NDIM 151
#define KNEI 10
#define HDIM 512
#define FB 5
#define FA 89
#define FAP 128                   // padded embed K
#define MN (BDIM * NDIM)          // 11476 nodes
#define LDU2 (HDIM + FB)          // 517
#define LDU1 (2 * HDIM)           // 1024
#define DEPTH 3

// ---------------- static device scratch (no allocation allowed) -------------
__device__ __align__(128) float g_sbond[MN * 8];   // s0..s4, cnt, 1, 0
__device__ __align__(128) float g_Wc[HDIM * 8];    // w0..w4, bc, b_U1, 0

// ping-pong feature buffers (bf16 hi/lo)
__device__ __align__(128) __nv_bfloat16 g_Ahi0[MN * HDIM], g_Alo0[MN * HDIM];
__device__ __align__(128) __nv_bfloat16 g_Ahi1[MN * HDIM], g_Alo1[MN * HDIM];
__device__ __align__(128) __nv_bfloat16 g_GGhi[MN * HDIM], g_GGlo[MN * HDIM];
__device__ __align__(128) __nv_bfloat16 g_Wahi[HDIM * HDIM], g_Walo[HDIM * HDIM];
__device__ __align__(128) __nv_bfloat16 g_Wbhi[HDIM * HDIM], g_Wblo[HDIM * HDIM];
__device__ __align__(128) __nv_bfloat16 g_Wfhi[HDIM * HDIM], g_Wflo[HDIM * HDIM];
__device__ __align__(128) __nv_bfloat16 g_Wthi[HDIM * HDIM], g_Wtlo[HDIM * HDIM];
// padded embed operands
__device__ __align__(128) __nv_bfloat16 g_Pahi[MN * FAP], g_Palo[MN * FAP];
__device__ __align__(128) __nv_bfloat16 g_PWhi[HDIM * FAP], g_PWlo[HDIM * FAP];

// ======================= PTX helpers (sm_80-safe only) ======================
__device__ __forceinline__ uint32_t smem_u32(const void* p) {
    uint32_t a;
    asm("{ .reg .u64 t; cvta.to.shared.u64 t, %1; cvt.u32.u64 %0, t; }"
        : "=r"(a) : "l"(p));
    return a;
}
__device__ __forceinline__ void cp_async16(uint32_t dst, const void* src, int sz) {
    asm volatile("cp.async.cg.shared.global [%0], [%1], 16, %2;"
                 :: "r"(dst), "l"(src), "r"(sz) : "memory");
}
__device__ __forceinline__ void ldsm_x4(uint32_t addr, uint32_t* r) {
    asm volatile("ldmatrix.sync.aligned.m8n8.x4.shared.b16 {%0,%1,%2,%3}, [%4];"
                 : "=r"(r[0]), "=r"(r[1]), "=r"(r[2]), "=r"(r[3]) : "r"(addr));
}
__device__ __forceinline__ void mma_bf16(float* c, const uint32_t* a,
                                         uint32_t b0, uint32_t b1) {
    asm volatile(
        "mma.sync.aligned.m16n8k16.row.col.f32.bf16.bf16.f32 "
        "{%0,%1,%2,%3}, {%4,%5,%6,%7}, {%8,%9}, {%0,%1,%2,%3};"
        : "+f"(c[0]), "+f"(c[1]), "+f"(c[2]), "+f"(c[3])
        : "r"(a[0]), "r"(a[1]), "r"(a[2]), "r"(a[3]), "r"(b0), "r"(b1));
}
__device__ __forceinline__ __nv_bfloat162 split_hi2(float x, float y,
                                                    __nv_bfloat162& lo2) {
    const __nv_bfloat16 hx = __float2bfloat16_rn(x);
    const __nv_bfloat16 hy = __float2bfloat16_rn(y);
    lo2 = __nv_bfloat162(__float2bfloat16_rn(x - __bfloat162float(hx)),
                         __float2bfloat16_rn(y - __bfloat162float(hy)));
    return __nv_bfloat162(hx, hy);
}
__device__ __forceinline__ float dot8(const float* s, const float* w) {
    return s[0]*w[0] + s[1]*w[1] + s[2]*w[2] + s[3]*w[3]
         + s[4]*w[4] + s[5]*w[5] + s[6]*w[6] + s[7]*w[7];
}

// ================= fused bf16x3 mma GEMM (operand-shared) ===================
// Per group g: C += Ahi_g@Bhi_g^T + Alo_g@Bhi_g^T + Ahi_g@Blo_g^T
// Stage = {Ahi, Alo, Bhi, Blo} tiles of one 64-K chunk (4 x 16KB = 64KB),
// 3 MMA passes per stage.  3-stage cp.async pipe (192KB smem, 1 CTA/SM).
// 256 threads = 8 warps in 4(m) x 2(n); CTA tile 128x128, warp tile 32x64.
// RANK8: add sbond8[gm] . wc8[gn] (fused CONST).  SPLIT: bf16 hi/lo output.
#define STG3_BYTES 65536
#define SMEM3 (3 * STG3_BYTES)

struct GemmArgs3 {
    const __nv_bfloat16 *ahi[2], *alo[2], *bhi[2], *blo[2];
};

template <int NGROUPS, int KCPP, int LDA, bool RANK8, bool SPLIT>
__global__ __launch_bounds__(256, 1)
void mma_gemm3(const GemmArgs3 args,
               float* __restrict__ C,
               __nv_bfloat16* __restrict__ Chi, __nv_bfloat16* __restrict__ Clo,
               const float* __restrict__ sbond8, const float* __restrict__ wc8,
               int M) {
    extern __shared__ __align__(128) char smem[];
    const uint32_t sbase = smem_u32(smem);
    const int tid = threadIdx.x, wid = tid >> 5, lane = tid & 31;
    const int bm = blockIdx.y * 128, bn = blockIdx.x * 128;
    const int wm = (wid & 3) * 32;
    const int wn = (wid >> 2) * 64;

    float acc[2][8][4] = {};

    const int lrow0 = tid >> 3;        // 0..31
    const int lch = tid & 7;           // 16B chunk within 128B row
    auto load_stage = [&](int g, int s) {
        const int grp = g / KCPP, kc = g % KCPP;
        const __nv_bfloat16* T[4] = { args.ahi[grp], args.alo[grp],
                                      args.bhi[grp], args.blo[grp] };
        const uint32_t sbs = sbase + s * STG3_BYTES;
        #pragma unroll
        for (int t = 0; t < 4; ++t) {
            const bool isA = (t < 2);
            const uint32_t tb = sbs + t * 16384;
            #pragma unroll
            for (int it = 0; it < 4; ++it) {
                const int row = lrow0 + it * 32;
                const uint32_t soff = row * 128 + ((lch ^ (row & 7)) << 4);
                const long gr = (isA ? bm : bn) + row;
                const int sz = (!isA || gr < M) ? 16 : 0;
                cp_async16(tb + soff, T[t] + gr * LDA + kc * 64 + lch * 8, sz);
            }
        }
        asm volatile("cp.async.commit_group;" ::: "memory");
    };

    auto compute_stage = [&](int s) {
        const uint32_t sah = sbase + s * STG3_BYTES;
        const uint32_t sal = sah + 16384;
        const uint32_t sbh = sah + 32768;
        const uint32_t sbl = sah + 49152;
        #pragma unroll
        for (int ks = 0; ks < 4; ++ks) {
            const int arow = wm + (lane & 15);
            const int ach = ks * 2 + (lane >> 4);
            uint32_t rah[2][4], ral[2][4];
            #pragma unroll
            for (int mb = 0; mb < 2; ++mb) {
                const int row = arow + mb * 16;
                const uint32_t off = row * 128 + ((ach ^ (row & 7)) << 4);
                ldsm_x4(sah + off, rah[mb]);
                ldsm_x4(sal + off, ral[mb]);
            }
            uint32_t rbh[4][4], rbl[4][4];
            #pragma unroll
            for (int nb = 0; nb < 4; ++nb) {
                const int row = wn + nb * 16 + (lane & 15);
                const uint32_t off = row * 128 + ((ach ^ (row & 7)) << 4);
                ldsm_x4(sbh + off, rbh[nb]);
                ldsm_x4(sbl + off, rbl[nb]);
            }
            #pragma unroll
            for (int mb = 0; mb < 2; ++mb)
                #pragma unroll
                for (int nb = 0; nb < 4; ++nb) {
                    // pass 1: hi x hi
                    mma_bf16(acc[mb][nb * 2],     rah[mb], rbh[nb][0], rbh[nb][2]);
                    mma_bf16(acc[mb][nb * 2 + 1], rah[mb], rbh[nb][1], rbh[nb][3]);
                    // pass 2: lo x hi
                    mma_bf16(acc[mb][nb * 2],     ral[mb], rbh[nb][0], rbh[nb][2]);
                    mma_bf16(acc[mb][nb * 2 + 1], ral[mb], rbh[nb][1], rbh[nb][3]);
                    // pass 3: hi x lo
                    mma_bf16(acc[mb][nb * 2],     rah[mb], rbl[nb][0], rbl[nb][2]);
                    mma_bf16(acc[mb][nb * 2 + 1], rah[mb], rbl[nb][1], rbl[nb][3]);
                }
        }
    };

    const int NG = NGROUPS * KCPP;
    load_stage(0, 0);
    if (NG > 1) load_stage(1, 1);
    for (int g = 0; g < NG; ++g) {
        if (g == NG - 1)
            asm volatile("cp.async.wait_group 0;" ::: "memory");
        else
            asm volatile("cp.async.wait_group 1;" ::: "memory");
        __syncthreads();
        compute_stage(g % 3);
        __syncthreads();
        if (g + 2 < NG) load_stage(g + 2, (g + 2) % 3);
    }

    // ---- epilogue ----
    float sb[4][8];
    if (RANK8) {
        #pragma unroll
        for (int r = 0; r < 4; ++r) {
            const int gm = bm + wm + (r >> 1) * 16 + (lane >> 2) + (r & 1) * 8;
            if (gm < M) {
                *(float4*)&sb[r][0] = *(const float4*)&sbond8[gm * 8];
                *(float4*)&sb[r][4] = *(const float4*)&sbond8[gm * 8 + 4];
            }
        }
    }
    #pragma unroll
    for (int nb = 0; nb < 8; ++nb) {
        const int gn = bn + wn + nb * 8 + (lane & 3) * 2;
        float w0[8], w1[8];
        if (RANK8) {
            *(float4*)&w0[0] = *(const float4*)&wc8[gn * 8];
            *(float4*)&w0[4] = *(const float4*)&wc8[gn * 8 + 4];
            *(float4*)&w1[0] = *(const float4*)&wc8[(gn + 1) * 8];
            *(float4*)&w1[4] = *(const float4*)&wc8[(gn + 1) * 8 + 4];
        }
        #pragma unroll
        for (int mb = 0; mb < 2; ++mb)
            #pragma unroll
            for (int h = 0; h < 2; ++h) {
                const int gm = bm + wm + mb * 16 + (lane >> 2) + h * 8;
                if (gm < M) {
                    const int r = mb * 2 + h;
                    float vx = acc[mb][nb][h * 2];
                    float vy = acc[mb][nb][h * 2 + 1];
                    if (RANK8) {
                        vx += dot8(sb[r], w0);
                        vy += dot8(sb[r], w1);
                    }
                    if (SPLIT) {
                        __nv_bfloat162 lo2;
                        const __nv_bfloat162 hi2 = split_hi2(vx, vy, lo2);
                        *(__nv_bfloat162*)&Chi[(long)gm * 512 + gn] = hi2;
                        *(__nv_bfloat162*)&Clo[(long)gm * 512 + gn] = lo2;
                    } else {
                        *(float2*)&C[(long)gm * 512 + gn] = make_float2(vx, vy);
                    }
                }
            }
    }
}

// ======================= small kernels ======================================
__global__ void gather_split_kernel(const __nv_bfloat16* __restrict__ Ahi,
                                    const __nv_bfloat16* __restrict__ Alo,
                                    const int* __restrict__ aidx,
                                    const int* __restrict__ num_nbs,
                                    __nv_bfloat16* __restrict__ Ghi,
                                    __nv_bfloat16* __restrict__ Glo) {
    const int node = blockIdx.x;
    const int base = (node / NDIM) * NDIM;
    const int e0 = threadIdx.x * 4;
    const int nn = num_nbs[node];
    float s0 = 0.f, s1 = 0.f, s2 = 0.f, s3 = 0.f;
    #pragma unroll
    for (int k = 0; k < KNEI; ++k) {
        if (k >= nn) break;
        const int idx = __ldg(&aidx[((long)node * KNEI + k) * 2]);
        const long ro = (long)(base + idx) * HDIM + e0;
        const __nv_bfloat162 h0 = *(const __nv_bfloat162*)&Ahi[ro];
        const __nv_bfloat162 h1 = *(const __nv_bfloat162*)&Ahi[ro + 2];
        const __nv_bfloat162 l0 = *(const __nv_bfloat162*)&Alo[ro];
        const __nv_bfloat162 l1 = *(const __nv_bfloat162*)&Alo[ro + 2];
        s0 += __low2float(h0)  + __low2float(l0);
        s1 += __high2float(h0) + __high2float(l0);
        s2 += __low2float(h1)  + __low2float(l1);
        s3 += __high2float(h1) + __high2float(l1);
    }
    const long wo = (long)node * HDIM + e0;
    __nv_bfloat162 lo2a, lo2b;
    const __nv_bfloat162 hi2a = split_hi2(s0, s1, lo2a);
    const __nv_bfloat162 hi2b = split_hi2(s2, s3, lo2b);
    *(__nv_bfloat162*)&Ghi[wo]     = hi2a;
    *(__nv_bfloat162*)&Ghi[wo + 2] = hi2b;
    *(__nv_bfloat162*)&Glo[wo]     = lo2a;
    *(__nv_bfloat162*)&Glo[wo + 2] = lo2b;
}

// sbond8[node] = {s0..s4, cnt, 1, 0}
__global__ void sbond_kernel(const float* __restrict__ input_bond,
                             const int* __restrict__ bidx,
                             const int* __restrict__ num_nbs,
                             float* __restrict__ sbond) {
    const int node = blockIdx.x * blockDim.x + threadIdx.x;
    if (node >= MN) return;
    const int base = (node / NDIM) * NDIM;
    const int nn = num_nbs[node];
    float s[FB] = {};
    for (int k = 0; k < nn; ++k) {
        const int idx = __ldg(&bidx[((long)node * KNEI + k) * 2]);
        const float* r = input_bond + (long)(base + idx) * FB;
        #pragma unroll
        for (int f = 0; f < FB; ++f) s[f] += __ldg(&r[f]);
    }
    *(float4*)&sbond[node * 8]     = make_float4(s[0], s[1], s[2], s[3]);
    *(float4*)&sbond[node * 8 + 4] = make_float4(s[4], (float)nn, 1.f, 0.f);
}

// wc8[h] = {Wc[h][0..4], bc[h], b_U1[h], 0};  Wc = W_U1b@W_U2b, bc = W_U1b@b_U2
__global__ void wc_kernel(const float* __restrict__ W_U1,
                          const float* __restrict__ W_U2,
                          const float* __restrict__ b_U2,
                          const float* __restrict__ b_U1,
                          float* __restrict__ Wc) {
    const int h = blockIdx.x * 2 + (threadIdx.x >> 5);   // 256 blocks x 64 thr
    const int lane = threadIdx.x & 31;
    float acc[6] = {};
    for (int m = lane; m < HDIM; m += 32) {
        const float u = __ldg(&W_U1[(long)h * LDU1 + HDIM + m]);
        #pragma unroll
        for (int f = 0; f < FB; ++f)
            acc[f] += u * __ldg(&W_U2[(long)m * LDU2 + HDIM + f]);
        acc[5] += u * __ldg(&b_U2[m]);
    }
    #pragma unroll
    for (int f = 0; f < 6; ++f)
        #pragma unroll
        for (int o = 16; o; o >>= 1)
            acc[f] += __shfl_xor_sync(0xFFFFFFFF, acc[f], o);
    if (lane == 0) {
        *(float4*)&Wc[h * 8] = make_float4(acc[0], acc[1], acc[2], acc[3]);
        *(float4*)&Wc[h * 8 + 4] = make_float4(acc[4], acc[5],
                                               __ldg(&b_U1[h]), 0.f);
    }
}

// transpose W_U2[:, 0:512] (ld=517) -> Wt[j][m] = W_U2[m][j], emit bf16 hi/lo
__global__ void transpose_split_kernel(const float* __restrict__ W,
                                       __nv_bfloat16* __restrict__ Thi,
                                       __nv_bfloat16* __restrict__ Tlo) {
    __shared__ float t[32][33];
    const int bx = blockIdx.x * 32, by = blockIdx.y * 32;
    const int x = threadIdx.x, y = threadIdx.y;    // 32 x 8
    #pragma unroll
    for (int i = 0; i < 32; i += 8)
        t[y + i][x] = __ldg(&W[(long)(by + y + i) * LDU2 + bx + x]);
    __syncthreads();
    #pragma unroll
    for (int i = 0; i < 32; i += 8) {
        const float v = t[x][y + i];
        const __nv_bfloat16 h = __float2bfloat16_rn(v);
        const long o = (long)(bx + y + i) * HDIM + by + x;
        Thi[o] = h;
        Tlo[o] = __float2bfloat16_rn(v - __bfloat162float(h));
    }
}

// strided weight split: out[n*512 + k] = W[n*ldw + koff + k]
__global__ void split_w_kernel(const float* __restrict__ W, int ldw, int koff,
                               __nv_bfloat16* __restrict__ hi,
                               __nv_bfloat16* __restrict__ lo) {
    const int idx = blockIdx.x * blockDim.x + threadIdx.x;
    if (idx >= HDIM * HDIM) return;
    const int n = idx >> 9, k = idx & 511;
    const float v = __ldg(&W[(long)n * ldw + koff + k]);
    const __nv_bfloat16 h = __float2bfloat16_rn(v);
    hi[idx] = h;
    lo[idx] = __float2bfloat16_rn(v - __bfloat162float(h));
}

// zero-padded split: [rows, cols] fp32 -> [rows, 128] bf16 hi/lo
__global__ void split_pad_kernel(const float* __restrict__ X, int rows, int cols,
                                 __nv_bfloat16* __restrict__ hi,
                                 __nv_bfloat16* __restrict__ lo) {
    const int idx = blockIdx.x * blockDim.x + threadIdx.x;
    if (idx >= rows * FAP) return;
    const int r = idx >> 7, c = idx & 127;
    const float v = (c < cols) ? __ldg(&X[(long)r * cols + c]) : 0.f;
    const __nv_bfloat16 h = __float2bfloat16_rn(v);
    hi[idx] = h;
    lo[idx] = __float2bfloat16_rn(v - __bfloat162float(h));
}

// ======================= host ===============================================
extern "C" void kernel_launch(void* const* d_in, const int* in_sizes, int n_in,
                              void* d_out, int out_size) {
    const float* input_atom = (const float*)d_in[0];
    const float* input_bond = (const float*)d_in[1];
    const int*   atom_nei   = (const int*)d_in[2];
    const int*   bond_nei   = (const int*)d_in[3];
    const int*   num_nbs    = (const int*)d_in[4];
    const float* W_atom     = (const float*)d_in[5];
    const float* W_U2       = (const float*)d_in[6];
    const float* b_U2       = (const float*)d_in[7];
    const float* W_U1       = (const float*)d_in[8];
    const float* b_U1       = (const float*)d_in[9];
    float* out = (float*)d_out;

    float *sbond, *Wc;
    cudaGetSymbolAddress((void**)&sbond, g_sbond);
    cudaGetSymbolAddress((void**)&Wc, g_Wc);
    __nv_bfloat16 *Ahi0, *Alo0, *Ahi1, *Alo1, *GGhi, *GGlo;
    __nv_bfloat16 *Wahi, *Walo, *Wbhi, *Wblo, *Wfhi, *Wflo, *Wthi, *Wtlo;
    __nv_bfloat16 *Pahi, *Palo, *PWhi, *PWlo;
    cudaGetSymbolAddress((void**)&Ahi0, g_Ahi0); cudaGetSymbolAddress((void**)&Alo0, g_Alo0);
    cudaGetSymbolAddress((void**)&Ahi1, g_Ahi1); cudaGetSymbolAddress((void**)&Alo1, g_Alo1);
    cudaGetSymbolAddress((void**)&GGhi, g_GGhi); cudaGetSymbolAddress((void**)&GGlo, g_GGlo);
    cudaGetSymbolAddress((void**)&Wahi, g_Wahi); cudaGetSymbolAddress((void**)&Walo, g_Walo);
    cudaGetSymbolAddress((void**)&Wbhi, g_Wbhi); cudaGetSymbolAddress((void**)&Wblo, g_Wblo);
    cudaGetSymbolAddress((void**)&Wfhi, g_Wfhi); cudaGetSymbolAddress((void**)&Wflo, g_Wflo);
    cudaGetSymbolAddress((void**)&Wthi, g_Wthi); cudaGetSymbolAddress((void**)&Wtlo, g_Wtlo);
    cudaGetSymbolAddress((void**)&Pahi, g_Pahi); cudaGetSymbolAddress((void**)&Palo, g_Palo);
    cudaGetSymbolAddress((void**)&PWhi, g_PWhi); cudaGetSymbolAddress((void**)&PWlo, g_PWlo);

    cudaFuncSetAttribute((const void*)mma_gemm3<1, 2, 128, false, true>,
                         cudaFuncAttributeMaxDynamicSharedMemorySize, SMEM3);
    cudaFuncSetAttribute((const void*)mma_gemm3<1, 8, 512, false, true>,
                         cudaFuncAttributeMaxDynamicSharedMemorySize, SMEM3);
    cudaFuncSetAttribute((const void*)mma_gemm3<2, 8, 512, true, true>,
                         cudaFuncAttributeMaxDynamicSharedMemorySize, SMEM3);
    cudaFuncSetAttribute((const void*)mma_gemm3<2, 8, 512, true, false>,
                         cudaFuncAttributeMaxDynamicSharedMemorySize, SMEM3);

    const dim3 thr(256);
    const dim3 grid_main(HDIM / 128, (MN + 127) / 128);   // 4 x 90
    const dim3 grid_sq(HDIM / 128, HDIM / 128);           // 4 x 4
    const int wblocks = (HDIM * HDIM + 255) / 256;

    // 1-2. Pad+split embed operands
    split_pad_kernel<<<(MN * FAP + 255) / 256, 256>>>(input_atom, MN, FA, Pahi, Palo);
    split_pad_kernel<<<(HDIM * FAP + 255) / 256, 256>>>(W_atom, HDIM, FA, PWhi, PWlo);

    // 3-4. Bond rank-8 fold precompute
    sbond_kernel<<<(MN + 127) / 128, 128>>>(input_bond, bond_nei, num_nbs, sbond);
    wc_kernel<<<HDIM / 2, 64>>>(W_U1, W_U2, b_U2, b_U1, Wc);

    // 5. Embed: A0(hi/lo) = input_atom @ W_atom^T  (bf16x3)
    {
        GemmArgs3 p{};
        p.ahi[0] = Pahi; p.alo[0] = Palo; p.bhi[0] = PWhi; p.blo[0] = PWlo;
        mma_gemm3<1, 2, 128, false, true><<<grid_main, thr, SMEM3>>>(
            p, nullptr, Ahi0, Alo0, nullptr, nullptr, MN);
    }

    // 6-8. Weight prep
    transpose_split_kernel<<<dim3(16, 16), dim3(32, 8)>>>(W_U2, Wthi, Wtlo);
    split_w_kernel<<<wblocks, 256>>>(W_U1, LDU1, 0, Wahi, Walo);
    split_w_kernel<<<wblocks, 256>>>(W_U1, LDU1, HDIM, Wbhi, Wblo);

    // 9. Fold: Wf(hi/lo) = W_U1b @ W_U2a  (bf16x3, split epilogue)
    {
        GemmArgs3 p{};
        p.ahi[0] = Wbhi; p.alo[0] = Wblo; p.bhi[0] = Wthi; p.blo[0] = Wtlo;
        mma_gemm3<1, 8, 512, false, true><<<grid_sq, thr, SMEM3>>>(
            p, nullptr, Wfhi, Wflo, nullptr, nullptr, HDIM);
    }

    // 10+. depth: GG = gather(A); A' = A@W_U1a^T + GG@Wf^T + sbond8.wc8
    __nv_bfloat16* srcHi = Ahi0;
    __nv_bfloat16* srcLo = Alo0;
    for (int d = 0; d < DEPTH; ++d) {
        gather_split_kernel<<<MN, 128>>>(srcHi, srcLo, atom_nei, num_nbs,
                                         GGhi, GGlo);
        GemmArgs3 p{};
        p.ahi[0] = srcHi; p.alo[0] = srcLo; p.bhi[0] = Wahi; p.blo[0] = Walo;
        p.ahi[1] = GGhi;  p.alo[1] = GGlo;  p.bhi[1] = Wfhi; p.blo[1] = Wflo;
        if (d == DEPTH - 1) {
            mma_gemm3<2, 8, 512, true, false><<<grid_main, thr, SMEM3>>>(
                p, out, nullptr, nullptr, sbond, Wc, MN);
        } else {
            __nv_bfloat16* dstHi = (srcHi == Ahi0) ? Ahi1 : Ahi0;
            __nv_bfloat16* dstLo = (srcLo == Alo0) ? Alo1 : Alo0;
            mma_gemm3<2, 8, 512, true, true><<<grid_main, thr, SMEM3>>>(
                p, nullptr, dstHi, dstLo, sbond, Wc, MN);
            srcHi = dstHi; srcLo = dstLo;
        }
    }
}

// round 8
// speedup vs baseline: 1.5622x; 1.1743x over previous
#include <cuda_runtime.h>
#include <cuda_bf16.h>
#include <cstdint>

// Problem constants (fixed by the dataset)
#define BDIM 76
#define NDIM 151
#define KNEI 10
#define HDIM 512
#define FB 5
#define FA 89
#define FAP 128                   // padded embed K
#define MN (BDIM * NDIM)          // 11476 nodes
#define LDU2 (HDIM + FB)          // 517
#define LDU1 (2 * HDIM)           // 1024
#define DEPTH 3

// ---------------- static device scratch (no allocation allowed) -------------
__device__ __align__(128) float g_sbond[MN * 8];   // s0..s4, cnt, 1, 0
__device__ __align__(128) float g_Wc[HDIM * 8];    // w0..w4, bc, b_U1, 0

// ping-pong feature buffers (bf16 hi/lo)
__device__ __align__(128) __nv_bfloat16 g_Ahi0[MN * HDIM], g_Alo0[MN * HDIM];
__device__ __align__(128) __nv_bfloat16 g_Ahi1[MN * HDIM], g_Alo1[MN * HDIM];
__device__ __align__(128) __nv_bfloat16 g_GGhi[MN * HDIM], g_GGlo[MN * HDIM];
__device__ __align__(128) __nv_bfloat16 g_Wahi[HDIM * HDIM], g_Walo[HDIM * HDIM];
__device__ __align__(128) __nv_bfloat16 g_Wbhi[HDIM * HDIM], g_Wblo[HDIM * HDIM];
__device__ __align__(128) __nv_bfloat16 g_Wfhi[HDIM * HDIM], g_Wflo[HDIM * HDIM];
__device__ __align__(128) __nv_bfloat16 g_Wthi[HDIM * HDIM], g_Wtlo[HDIM * HDIM];
// padded embed operands
__device__ __align__(128) __nv_bfloat16 g_Pahi[MN * FAP], g_Palo[MN * FAP];
__device__ __align__(128) __nv_bfloat16 g_PWhi[HDIM * FAP], g_PWlo[HDIM * FAP];

// ======================= PTX helpers (sm_80-safe only) ======================
__device__ __forceinline__ uint32_t smem_u32(const void* p) {
    uint32_t a;
    asm("{ .reg .u64 t; cvta.to.shared.u64 t, %1; cvt.u32.u64 %0, t; }"
        : "=r"(a) : "l"(p));
    return a;
}
__device__ __forceinline__ void cp_async16(uint32_t dst, const void* src, int sz) {
    asm volatile("cp.async.cg.shared.global [%0], [%1], 16, %2;"
                 :: "r"(dst), "l"(src), "r"(sz) : "memory");
}
__device__ __forceinline__ void ldsm_x4(uint32_t addr, uint32_t* r) {
    asm volatile("ldmatrix.sync.aligned.m8n8.x4.shared.b16 {%0,%1,%2,%3}, [%4];"
                 : "=r"(r[0]), "=r"(r[1]), "=r"(r[2]), "=r"(r[3]) : "r"(addr));
}
__device__ __forceinline__ void mma_bf16(float* c, const uint32_t* a,
                                         uint32_t b0, uint32_t b1) {
    asm volatile(
        "mma.sync.aligned.m16n8k16.row.col.f32.bf16.bf16.f32 "
        "{%0,%1,%2,%3}, {%4,%5,%6,%7}, {%8,%9}, {%0,%1,%2,%3};"
        : "+f"(c[0]), "+f"(c[1]), "+f"(c[2]), "+f"(c[3])
        : "r"(a[0]), "r"(a[1]), "r"(a[2]), "r"(a[3]), "r"(b0), "r"(b1));
}
__device__ __forceinline__ __nv_bfloat162 split_hi2(float x, float y,
                                                    __nv_bfloat162& lo2) {
    const __nv_bfloat16 hx = __float2bfloat16_rn(x);
    const __nv_bfloat16 hy = __float2bfloat16_rn(y);
    lo2 = __nv_bfloat162(__float2bfloat16_rn(x - __bfloat162float(hx)),
                         __float2bfloat16_rn(y - __bfloat162float(hy)));
    return __nv_bfloat162(hx, hy);
}
__device__ __forceinline__ float dot8(const float* s, const float* w) {
    return s[0]*w[0] + s[1]*w[1] + s[2]*w[2] + s[3]*w[3]
         + s[4]*w[4] + s[5]*w[5] + s[6]*w[6] + s[7]*w[7];
}

// ============ fused bf16x3 mma GEMM, 128x64 tiles, 2 CTAs/SM ================
// Per group g: C += Ahi_g@Bhi_g^T + Alo_g@Bhi_g^T + Ahi_g@Blo_g^T
// Stage = {Ahi(16K), Alo(16K), Bhi(8K), Blo(8K)} of one 64-K chunk = 48KB.
// Double-buffered (2 stages, 96KB smem -> 2 CTAs/SM).
// 256 threads = 8 warps in 4(m) x 2(n); CTA tile 128x64, warp tile 32x32.
// RANK8: add sbond8[gm].wc8[gn] (fused CONST).  SPLIT: bf16 hi/lo output.
#define STG_BYTES 49152
#define SMEM_G (2 * STG_BYTES)

struct GemmArgs3 {
    const __nv_bfloat16 *ahi[2], *alo[2], *bhi[2], *blo[2];
};

template <int NGROUPS, int KCPP, int LDA, bool RANK8, bool SPLIT>
__global__ __launch_bounds__(256, 2)
void mma_gemm64(const GemmArgs3 args,
                float* __restrict__ C,
                __nv_bfloat16* __restrict__ Chi, __nv_bfloat16* __restrict__ Clo,
                const float* __restrict__ sbond8, const float* __restrict__ wc8,
                int M) {
    extern __shared__ __align__(128) char smem[];
    const uint32_t sbase = smem_u32(smem);
    const int tid = threadIdx.x, wid = tid >> 5, lane = tid & 31;
    const int bm = blockIdx.y * 128, bn = blockIdx.x * 64;
    const int wm = (wid & 3) * 32;
    const int wn = (wid >> 2) * 32;

    float acc[2][4][4] = {};

    const int lrow0 = tid >> 3;        // 0..31
    const int lch = tid & 7;           // 16B chunk within 128B row
    auto load_stage = [&](int g, int s) {
        const int grp = g / KCPP, kc = g % KCPP;
        const uint32_t sbs = sbase + s * STG_BYTES;
        // A tiles: 128 rows x 128B each (hi @0, lo @16K)
        const __nv_bfloat16* TA[2] = { args.ahi[grp], args.alo[grp] };
        #pragma unroll
        for (int t = 0; t < 2; ++t) {
            const uint32_t tb = sbs + t * 16384;
            #pragma unroll
            for (int it = 0; it < 4; ++it) {
                const int row = lrow0 + it * 32;
                const uint32_t soff = row * 128 + ((lch ^ (row & 7)) << 4);
                const long gr = bm + row;
                cp_async16(tb + soff, TA[t] + gr * LDA + kc * 64 + lch * 8,
                           (gr < M) ? 16 : 0);
            }
        }
        // B tiles: 64 rows x 128B each (hi @32K, lo @40K)
        const __nv_bfloat16* TB[2] = { args.bhi[grp], args.blo[grp] };
        #pragma unroll
        for (int t = 0; t < 2; ++t) {
            const uint32_t tb = sbs + 32768 + t * 8192;
            #pragma unroll
            for (int it = 0; it < 2; ++it) {
                const int row = lrow0 + it * 32;
                const uint32_t soff = row * 128 + ((lch ^ (row & 7)) << 4);
                const long gr = bn + row;
                cp_async16(tb + soff, TB[t] + gr * LDA + kc * 64 + lch * 8, 16);
            }
        }
        asm volatile("cp.async.commit_group;" ::: "memory");
    };

    auto compute_stage = [&](int s) {
        const uint32_t sah = sbase + s * STG_BYTES;
        const uint32_t sal = sah + 16384;
        const uint32_t sbh = sah + 32768;
        const uint32_t sbl = sah + 40960;
        #pragma unroll
        for (int ks = 0; ks < 4; ++ks) {
            const int ach = ks * 2 + (lane >> 4);
            uint32_t rah[2][4], ral[2][4];
            #pragma unroll
            for (int mb = 0; mb < 2; ++mb) {
                const int row = wm + mb * 16 + (lane & 15);
                const uint32_t off = row * 128 + ((ach ^ (row & 7)) << 4);
                ldsm_x4(sah + off, rah[mb]);
                ldsm_x4(sal + off, ral[mb]);
            }
            uint32_t rbh[2][4], rbl[2][4];
            #pragma unroll
            for (int nb = 0; nb < 2; ++nb) {
                const int row = wn + nb * 16 + (lane & 15);
                const uint32_t off = row * 128 + ((ach ^ (row & 7)) << 4);
                ldsm_x4(sbh + off, rbh[nb]);
                ldsm_x4(sbl + off, rbl[nb]);
            }
            #pragma unroll
            for (int mb = 0; mb < 2; ++mb)
                #pragma unroll
                for (int nb = 0; nb < 2; ++nb) {
                    mma_bf16(acc[mb][nb * 2],     rah[mb], rbh[nb][0], rbh[nb][2]);
                    mma_bf16(acc[mb][nb * 2 + 1], rah[mb], rbh[nb][1], rbh[nb][3]);
                    mma_bf16(acc[mb][nb * 2],     ral[mb], rbh[nb][0], rbh[nb][2]);
                    mma_bf16(acc[mb][nb * 2 + 1], ral[mb], rbh[nb][1], rbh[nb][3]);
                    mma_bf16(acc[mb][nb * 2],     rah[mb], rbl[nb][0], rbl[nb][2]);
                    mma_bf16(acc[mb][nb * 2 + 1], rah[mb], rbl[nb][1], rbl[nb][3]);
                }
        }
    };

    const int NG = NGROUPS * KCPP;
    load_stage(0, 0);
    for (int g = 0; g < NG; ++g) {
        if (g + 1 < NG) {
            load_stage(g + 1, (g + 1) & 1);
            asm volatile("cp.async.wait_group 1;" ::: "memory");
        } else {
            asm volatile("cp.async.wait_group 0;" ::: "memory");
        }
        __syncthreads();
        compute_stage(g & 1);
        __syncthreads();
    }

    // ---- epilogue ----
    float sb[4][8];
    if (RANK8) {
        #pragma unroll
        for (int r = 0; r < 4; ++r) {
            const int gm = bm + wm + (r >> 1) * 16 + (lane >> 2) + (r & 1) * 8;
            if (gm < M) {
                *(float4*)&sb[r][0] = *(const float4*)&sbond8[gm * 8];
                *(float4*)&sb[r][4] = *(const float4*)&sbond8[gm * 8 + 4];
            }
        }
    }
    #pragma unroll
    for (int nb = 0; nb < 4; ++nb) {
        const int gn = bn + wn + nb * 8 + (lane & 3) * 2;
        float w0[8], w1[8];
        if (RANK8) {
            *(float4*)&w0[0] = *(const float4*)&wc8[gn * 8];
            *(float4*)&w0[4] = *(const float4*)&wc8[gn * 8 + 4];
            *(float4*)&w1[0] = *(const float4*)&wc8[(gn + 1) * 8];
            *(float4*)&w1[4] = *(const float4*)&wc8[(gn + 1) * 8 + 4];
        }
        #pragma unroll
        for (int mb = 0; mb < 2; ++mb)
            #pragma unroll
            for (int h = 0; h < 2; ++h) {
                const int gm = bm + wm + mb * 16 + (lane >> 2) + h * 8;
                if (gm < M) {
                    const int r = mb * 2 + h;
                    float vx = acc[mb][nb][h * 2];
                    float vy = acc[mb][nb][h * 2 + 1];
                    if (RANK8) {
                        vx += dot8(sb[r], w0);
                        vy += dot8(sb[r], w1);
                    }
                    if (SPLIT) {
                        __nv_bfloat162 lo2;
                        const __nv_bfloat162 hi2 = split_hi2(vx, vy, lo2);
                        *(__nv_bfloat162*)&Chi[(long)gm * 512 + gn] = hi2;
                        *(__nv_bfloat162*)&Clo[(long)gm * 512 + gn] = lo2;
                    } else {
                        *(float2*)&C[(long)gm * 512 + gn] = make_float2(vx, vy);
                    }
                }
            }
    }
}

// ======================= small kernels ======================================
__global__ void gather_split_kernel(const __nv_bfloat16* __restrict__ Ahi,
                                    const __nv_bfloat16* __restrict__ Alo,
                                    const int* __restrict__ aidx,
                                    const int* __restrict__ num_nbs,
                                    __nv_bfloat16* __restrict__ Ghi,
                                    __nv_bfloat16* __restrict__ Glo) {
    const int node = blockIdx.x;
    const int base = (node / NDIM) * NDIM;
    const int e0 = threadIdx.x * 4;
    const int nn = num_nbs[node];
    float s0 = 0.f, s1 = 0.f, s2 = 0.f, s3 = 0.f;
    #pragma unroll
    for (int k = 0; k < KNEI; ++k) {
        if (k >= nn) break;
        const int idx = __ldg(&aidx[((long)node * KNEI + k) * 2]);
        const long ro = (long)(base + idx) * HDIM + e0;
        const __nv_bfloat162 h0 = *(const __nv_bfloat162*)&Ahi[ro];
        const __nv_bfloat162 h1 = *(const __nv_bfloat162*)&Ahi[ro + 2];
        const __nv_bfloat162 l0 = *(const __nv_bfloat162*)&Alo[ro];
        const __nv_bfloat162 l1 = *(const __nv_bfloat162*)&Alo[ro + 2];
        s0 += __low2float(h0)  + __low2float(l0);
        s1 += __high2float(h0) + __high2float(l0);
        s2 += __low2float(h1)  + __low2float(l1);
        s3 += __high2float(h1) + __high2float(l1);
    }
    const long wo = (long)node * HDIM + e0;
    __nv_bfloat162 lo2a, lo2b;
    const __nv_bfloat162 hi2a = split_hi2(s0, s1, lo2a);
    const __nv_bfloat162 hi2b = split_hi2(s2, s3, lo2b);
    *(__nv_bfloat162*)&Ghi[wo]     = hi2a;
    *(__nv_bfloat162*)&Ghi[wo + 2] = hi2b;
    *(__nv_bfloat162*)&Glo[wo]     = lo2a;
    *(__nv_bfloat162*)&Glo[wo + 2] = lo2b;
}

// sbond8[node] = {s0..s4, cnt, 1, 0}
__global__ void sbond_kernel(const float* __restrict__ input_bond,
                             const int* __restrict__ bidx,
                             const int* __restrict__ num_nbs,
                             float* __restrict__ sbond) {
    const int node = blockIdx.x * blockDim.x + threadIdx.x;
    if (node >= MN) return;
    const int base = (node / NDIM) * NDIM;
    const int nn = num_nbs[node];
    float s[FB] = {};
    for (int k = 0; k < nn; ++k) {
        const int idx = __ldg(&bidx[((long)node * KNEI + k) * 2]);
        const float* r = input_bond + (long)(base + idx) * FB;
        #pragma unroll
        for (int f = 0; f < FB; ++f) s[f] += __ldg(&r[f]);
    }
    *(float4*)&sbond[node * 8]     = make_float4(s[0], s[1], s[2], s[3]);
    *(float4*)&sbond[node * 8 + 4] = make_float4(s[4], (float)nn, 1.f, 0.f);
}

// wc8[h] = {Wc[h][0..4], bc[h], b_U1[h], 0};  Wc = W_U1b@W_U2b, bc = W_U1b@b_U2
// Block: 128 threads = 4 warps, warp per h (4 h per block, 128 blocks).
// W_U2b/b_U2 staged into smem once per block; W_U1b rows read coalesced.
__global__ void wc_kernel(const float* __restrict__ W_U1,
                          const float* __restrict__ W_U2,
                          const float* __restrict__ b_U2,
                          const float* __restrict__ b_U1,
                          float* __restrict__ Wc) {
    __shared__ float w2[HDIM * 6];
    const int tid = threadIdx.x;
    for (int e = tid; e < HDIM * 6; e += 128) {
        const int m = e / 6, f = e % 6;
        w2[e] = (f < FB) ? __ldg(&W_U2[(long)m * LDU2 + HDIM + f])
                         : __ldg(&b_U2[m]);
    }
    __syncthreads();
    const int h = blockIdx.x * 4 + (tid >> 5);
    const int lane = tid & 31;
    float acc[6] = {};
    for (int m = lane; m < HDIM; m += 32) {
        const float u = __ldg(&W_U1[(long)h * LDU1 + HDIM + m]);
        const float* w = &w2[m * 6];
        #pragma unroll
        for (int f = 0; f < 6; ++f) acc[f] += u * w[f];
    }
    #pragma unroll
    for (int f = 0; f < 6; ++f)
        #pragma unroll
        for (int o = 16; o; o >>= 1)
            acc[f] += __shfl_xor_sync(0xFFFFFFFF, acc[f], o);
    if (lane == 0) {
        *(float4*)&Wc[h * 8] = make_float4(acc[0], acc[1], acc[2], acc[3]);
        *(float4*)&Wc[h * 8 + 4] = make_float4(acc[4], acc[5],
                                               __ldg(&b_U1[h]), 0.f);
    }
}

// transpose W_U2[:, 0:512] (ld=517) -> Wt[j][m] = W_U2[m][j], emit bf16 hi/lo
__global__ void transpose_split_kernel(const float* __restrict__ W,
                                       __nv_bfloat16* __restrict__ Thi,
                                       __nv_bfloat16* __restrict__ Tlo) {
    __shared__ float t[32][33];
    const int bx = blockIdx.x * 32, by = blockIdx.y * 32;
    const int x = threadIdx.x, y = threadIdx.y;    // 32 x 8
    #pragma unroll
    for (int i = 0; i < 32; i += 8)
        t[y + i][x] = __ldg(&W[(long)(by + y + i) * LDU2 + bx + x]);
    __syncthreads();
    #pragma unroll
    for (int i = 0; i < 32; i += 8) {
        const float v = t[x][y + i];
        const __nv_bfloat16 h = __float2bfloat16_rn(v);
        const long o = (long)(bx + y + i) * HDIM + by + x;
        Thi[o] = h;
        Tlo[o] = __float2bfloat16_rn(v - __bfloat162float(h));
    }
}

// strided weight split: out[n*512 + k] = W[n*ldw + koff + k]
__global__ void split_w_kernel(const float* __restrict__ W, int ldw, int koff,
                               __nv_bfloat16* __restrict__ hi,
                               __nv_bfloat16* __restrict__ lo) {
    const int idx = blockIdx.x * blockDim.x + threadIdx.x;
    if (idx >= HDIM * HDIM) return;
    const int n = idx >> 9, k = idx & 511;
    const float v = __ldg(&W[(long)n * ldw + koff + k]);
    const __nv_bfloat16 h = __float2bfloat16_rn(v);
    hi[idx] = h;
    lo[idx] = __float2bfloat16_rn(v - __bfloat162float(h));
}

// zero-padded split: [rows, cols] fp32 -> [rows, 128] bf16 hi/lo
__global__ void split_pad_kernel(const float* __restrict__ X, int rows, int cols,
                                 __nv_bfloat16* __restrict__ hi,
                                 __nv_bfloat16* __restrict__ lo) {
    const int idx = blockIdx.x * blockDim.x + threadIdx.x;
    if (idx >= rows * FAP) return;
    const int r = idx >> 7, c = idx & 127;
    const float v = (c < cols) ? __ldg(&X[(long)r * cols + c]) : 0.f;
    const __nv_bfloat16 h = __float2bfloat16_rn(v);
    hi[idx] = h;
    lo[idx] = __float2bfloat16_rn(v - __bfloat162float(h));
}

// ======================= host ===============================================
extern "C" void kernel_launch(void* const* d_in, const int* in_sizes, int n_in,
                              void* d_out, int out_size) {
    const float* input_atom = (const float*)d_in[0];
    const float* input_bond = (const float*)d_in[1];
    const int*   atom_nei   = (const int*)d_in[2];
    const int*   bond_nei   = (const int*)d_in[3];
    const int*   num_nbs    = (const int*)d_in[4];
    const float* W_atom     = (const float*)d_in[5];
    const float* W_U2       = (const float*)d_in[6];
    const float* b_U2       = (const float*)d_in[7];
    const float* W_U1       = (const float*)d_in[8];
    const float* b_U1       = (const float*)d_in[9];
    float* out = (float*)d_out;

    float *sbond, *Wc;
    cudaGetSymbolAddress((void**)&sbond, g_sbond);
    cudaGetSymbolAddress((void**)&Wc, g_Wc);
    __nv_bfloat16 *Ahi0, *Alo0, *Ahi1, *Alo1, *GGhi, *GGlo;
    __nv_bfloat16 *Wahi, *Walo, *Wbhi, *Wblo, *Wfhi, *Wflo, *Wthi, *Wtlo;
    __nv_bfloat16 *Pahi, *Palo, *PWhi, *PWlo;
    cudaGetSymbolAddress((void**)&Ahi0, g_Ahi0); cudaGetSymbolAddress((void**)&Alo0, g_Alo0);
    cudaGetSymbolAddress((void**)&Ahi1, g_Ahi1); cudaGetSymbolAddress((void**)&Alo1, g_Alo1);
    cudaGetSymbolAddress((void**)&GGhi, g_GGhi); cudaGetSymbolAddress((void**)&GGlo, g_GGlo);
    cudaGetSymbolAddress((void**)&Wahi, g_Wahi); cudaGetSymbolAddress((void**)&Walo, g_Walo);
    cudaGetSymbolAddress((void**)&Wbhi, g_Wbhi); cudaGetSymbolAddress((void**)&Wblo, g_Wblo);
    cudaGetSymbolAddress((void**)&Wfhi, g_Wfhi); cudaGetSymbolAddress((void**)&Wflo, g_Wflo);
    cudaGetSymbolAddress((void**)&Wthi, g_Wthi); cudaGetSymbolAddress((void**)&Wtlo, g_Wtlo);
    cudaGetSymbolAddress((void**)&Pahi, g_Pahi); cudaGetSymbolAddress((void**)&Palo, g_Palo);
    cudaGetSymbolAddress((void**)&PWhi, g_PWhi); cudaGetSymbolAddress((void**)&PWlo, g_PWlo);

    cudaFuncSetAttribute((const void*)mma_gemm64<1, 2, 128, false, true>,
                         cudaFuncAttributeMaxDynamicSharedMemorySize, SMEM_G);
    cudaFuncSetAttribute((const void*)mma_gemm64<1, 8, 512, false, true>,
                         cudaFuncAttributeMaxDynamicSharedMemorySize, SMEM_G);
    cudaFuncSetAttribute((const void*)mma_gemm64<2, 8, 512, true, true>,
                         cudaFuncAttributeMaxDynamicSharedMemorySize, SMEM_G);
    cudaFuncSetAttribute((const void*)mma_gemm64<2, 8, 512, true, false>,
                         cudaFuncAttributeMaxDynamicSharedMemorySize, SMEM_G);

    const dim3 thr(256);
    const dim3 grid_main(HDIM / 64, (MN + 127) / 128);    // 8 x 90 = 720
    const dim3 grid_sq(HDIM / 64, HDIM / 128);            // 8 x 4 = 32
    const int wblocks = (HDIM * HDIM + 255) / 256;

    // 1-2. Pad+split embed operands
    split_pad_kernel<<<(MN * FAP + 255) / 256, 256>>>(input_atom, MN, FA, Pahi, Palo);
    split_pad_kernel<<<(HDIM * FAP + 255) / 256, 256>>>(W_atom, HDIM, FA, PWhi, PWlo);

    // 3-4. Bond rank-8 fold precompute
    sbond_kernel<<<(MN + 127) / 128, 128>>>(input_bond, bond_nei, num_nbs, sbond);
    wc_kernel<<<HDIM / 4, 128>>>(W_U1, W_U2, b_U2, b_U1, Wc);

    // 5. Embed: A0(hi/lo) = input_atom @ W_atom^T  (bf16x3)
    {
        GemmArgs3 p{};
        p.ahi[0] = Pahi; p.alo[0] = Palo; p.bhi[0] = PWhi; p.blo[0] = PWlo;
        mma_gemm64<1, 2, 128, false, true><<<grid_main, thr, SMEM_G>>>(
            p, nullptr, Ahi0, Alo0, nullptr, nullptr, MN);
    }

    // 6-8. Weight prep
    transpose_split_kernel<<<dim3(16, 16), dim3(32, 8)>>>(W_U2, Wthi, Wtlo);
    split_w_kernel<<<wblocks, 256>>>(W_U1, LDU1, 0, Wahi, Walo);
    split_w_kernel<<<wblocks, 256>>>(W_U1, LDU1, HDIM, Wbhi, Wblo);

    // 9. Fold: Wf(hi/lo) = W_U1b @ W_U2a  (bf16x3, split epilogue)
    {
        GemmArgs3 p{};
        p.ahi[0] = Wbhi; p.alo[0] = Wblo; p.bhi[0] = Wthi; p.blo[0] = Wtlo;
        mma_gemm64<1, 8, 512, false, true><<<grid_sq, thr, SMEM_G>>>(
            p, nullptr, Wfhi, Wflo, nullptr, nullptr, HDIM);
    }

    // 10+. depth: GG = gather(A); A' = A@W_U1a^T + GG@Wf^T + sbond8.wc8
    __nv_bfloat16* srcHi = Ahi0;
    __nv_bfloat16* srcLo = Alo0;
    for (int d = 0; d < DEPTH; ++d) {
        gather_split_kernel<<<MN, 128>>>(srcHi, srcLo, atom_nei, num_nbs,
                                         GGhi, GGlo);
        GemmArgs3 p{};
        p.ahi[0] = srcHi; p.alo[0] = srcLo; p.bhi[0] = Wahi; p.blo[0] = Walo;
        p.ahi[1] = GGhi;  p.alo[1] = GGlo;  p.bhi[1] = Wfhi; p.blo[1] = Wflo;
        if (d == DEPTH - 1) {
            mma_gemm64<2, 8, 512, true, false><<<grid_main, thr, SMEM_G>>>(
                p, out, nullptr, nullptr, sbond, Wc, MN);
        } else {
            __nv_bfloat16* dstHi = (srcHi == Ahi0) ? Ahi1 : Ahi0;
            __nv_bfloat16* dstLo = (srcLo == Alo0) ? Alo1 : Alo0;
            mma_gemm64<2, 8, 512, true, true><<<grid_main, thr, SMEM_G>>>(
                p, nullptr, dstHi, dstLo, sbond, Wc, MN);
            srcHi = dstHi; srcLo = dstLo;
        }
    }
}

// round 9
// speedup vs baseline: 1.9261x; 1.2330x over previous
#include <cuda_runtime.h>
#include <cuda_bf16.h>
#include <cstdint>

// Problem constants (fixed by the dataset)
#define BDIM 76
#define NDIM 151
#define KNEI 10
#define HDIM 512
#define FB 5
#define FA 89
#define FAP 128                   // padded raw-input K
#define MN (BDIM * NDIM)          // 11476 nodes
#define LDU2 (HDIM + FB)          // 517
#define LDU1 (2 * HDIM)           // 1024
#define DEPTH 3

// ---------------- static device scratch (no allocation allowed) -------------
__device__ __align__(128) float g_sbond[MN * 8];   // s0..s4, cnt, 1, 0
__device__ __align__(128) float g_Wc[HDIM * 8];    // w0..w4, bc, b_U1, 0

// ping-pong feature buffers (bf16 hi/lo)
__device__ __align__(128) __nv_bfloat16 g_Ahi0[MN * HDIM], g_Alo0[MN * HDIM];
__device__ __align__(128) __nv_bfloat16 g_Ahi1[MN * HDIM], g_Alo1[MN * HDIM];
__device__ __align__(128) __nv_bfloat16 g_GGhi[MN * HDIM], g_GGlo[MN * HDIM];
__device__ __align__(128) __nv_bfloat16 g_Wahi[HDIM * HDIM], g_Walo[HDIM * HDIM];
__device__ __align__(128) __nv_bfloat16 g_Wbhi[HDIM * HDIM], g_Wblo[HDIM * HDIM];
__device__ __align__(128) __nv_bfloat16 g_Wfhi[HDIM * HDIM], g_Wflo[HDIM * HDIM];
__device__ __align__(128) __nv_bfloat16 g_Wthi[HDIM * HDIM], g_Wtlo[HDIM * HDIM];
// padded raw input + its gather (bf16 hi/lo, K=128)
__device__ __align__(128) __nv_bfloat16 g_Pahi[MN * FAP], g_Palo[MN * FAP];
__device__ __align__(128) __nv_bfloat16 g_Pghi[MN * FAP], g_Pglo[MN * FAP];
// folded depth-0 weights [512,128] and We^T [128,512] (zero-init padding)
__device__ __align__(128) __nv_bfloat16 g_Wc1hi[HDIM * FAP], g_Wc1lo[HDIM * FAP];
__device__ __align__(128) __nv_bfloat16 g_Wfehi[HDIM * FAP], g_Wfelo[HDIM * FAP];
__device__ __align__(128) __nv_bfloat16 g_Wethi[FAP * HDIM], g_Wetlo[FAP * HDIM];

// ======================= PTX helpers (sm_80-safe only) ======================
__device__ __forceinline__ uint32_t smem_u32(const void* p) {
    uint32_t a;
    asm("{ .reg .u64 t; cvta.to.shared.u64 t, %1; cvt.u32.u64 %0, t; }"
        : "=r"(a) : "l"(p));
    return a;
}
__device__ __forceinline__ void cp_async16(uint32_t dst, const void* src, int sz) {
    asm volatile("cp.async.cg.shared.global [%0], [%1], 16, %2;"
                 :: "r"(dst), "l"(src), "r"(sz) : "memory");
}
__device__ __forceinline__ void ldsm_x4(uint32_t addr, uint32_t* r) {
    asm volatile("ldmatrix.sync.aligned.m8n8.x4.shared.b16 {%0,%1,%2,%3}, [%4];"
                 : "=r"(r[0]), "=r"(r[1]), "=r"(r[2]), "=r"(r[3]) : "r"(addr));
}
__device__ __forceinline__ void mma_bf16(float* c, const uint32_t* a,
                                         uint32_t b0, uint32_t b1) {
    asm volatile(
        "mma.sync.aligned.m16n8k16.row.col.f32.bf16.bf16.f32 "
        "{%0,%1,%2,%3}, {%4,%5,%6,%7}, {%8,%9}, {%0,%1,%2,%3};"
        : "+f"(c[0]), "+f"(c[1]), "+f"(c[2]), "+f"(c[3])
        : "r"(a[0]), "r"(a[1]), "r"(a[2]), "r"(a[3]), "r"(b0), "r"(b1));
}
__device__ __forceinline__ __nv_bfloat162 split_hi2(float x, float y,
                                                    __nv_bfloat162& lo2) {
    const __nv_bfloat16 hx = __float2bfloat16_rn(x);
    const __nv_bfloat16 hy = __float2bfloat16_rn(y);
    lo2 = __nv_bfloat162(__float2bfloat16_rn(x - __bfloat162float(hx)),
                         __float2bfloat16_rn(y - __bfloat162float(hy)));
    return __nv_bfloat162(hx, hy);
}
__device__ __forceinline__ float dot8(const float* s, const float* w) {
    return s[0]*w[0] + s[1]*w[1] + s[2]*w[2] + s[3]*w[3]
         + s[4]*w[4] + s[5]*w[5] + s[6]*w[6] + s[7]*w[7];
}

// ============ fused bf16x3 mma GEMM, 128x64 tiles, 2 CTAs/SM ================
// Per group g: C += Ahi_g@Bhi_g^T + Alo_g@Bhi_g^T + Ahi_g@Blo_g^T
// Stage = {Ahi(16K), Alo(16K), Bhi(8K), Blo(8K)} of one 64-K chunk = 48KB.
// Double-buffered (96KB smem -> 2 CTAs/SM).  256 thr = 8 warps 4(m) x 2(n).
// RANK8: add sbond8[gm].wc8[gn] (fused CONST).  SPLIT: bf16 hi/lo output.
#define STG_BYTES 49152
#define SMEM_G (2 * STG_BYTES)

struct GemmArgs3 {
    const __nv_bfloat16 *ahi[2], *alo[2], *bhi[2], *blo[2];
};

template <int NGROUPS, int KCPP, int LDA, int LDC, bool RANK8, bool SPLIT>
__global__ __launch_bounds__(256, 2)
void mma_gemm64(const GemmArgs3 args,
                float* __restrict__ C,
                __nv_bfloat16* __restrict__ Chi, __nv_bfloat16* __restrict__ Clo,
                const float* __restrict__ sbond8, const float* __restrict__ wc8,
                int M) {
    extern __shared__ __align__(128) char smem[];
    const uint32_t sbase = smem_u32(smem);
    const int tid = threadIdx.x, wid = tid >> 5, lane = tid & 31;
    const int bm = blockIdx.y * 128, bn = blockIdx.x * 64;
    const int wm = (wid & 3) * 32;
    const int wn = (wid >> 2) * 32;

    float acc[2][4][4] = {};

    const int lrow0 = tid >> 3;        // 0..31
    const int lch = tid & 7;           // 16B chunk within 128B row
    auto load_stage = [&](int g, int s) {
        const int grp = g / KCPP, kc = g % KCPP;
        const uint32_t sbs = sbase + s * STG_BYTES;
        const __nv_bfloat16* TA[2] = { args.ahi[grp], args.alo[grp] };
        #pragma unroll
        for (int t = 0; t < 2; ++t) {
            const uint32_t tb = sbs + t * 16384;
            #pragma unroll
            for (int it = 0; it < 4; ++it) {
                const int row = lrow0 + it * 32;
                const uint32_t soff = row * 128 + ((lch ^ (row & 7)) << 4);
                const long gr = bm + row;
                cp_async16(tb + soff, TA[t] + gr * LDA + kc * 64 + lch * 8,
                           (gr < M) ? 16 : 0);
            }
        }
        const __nv_bfloat16* TB[2] = { args.bhi[grp], args.blo[grp] };
        #pragma unroll
        for (int t = 0; t < 2; ++t) {
            const uint32_t tb = sbs + 32768 + t * 8192;
            #pragma unroll
            for (int it = 0; it < 2; ++it) {
                const int row = lrow0 + it * 32;
                const uint32_t soff = row * 128 + ((lch ^ (row & 7)) << 4);
                const long gr = bn + row;
                cp_async16(tb + soff, TB[t] + gr * LDA + kc * 64 + lch * 8, 16);
            }
        }
        asm volatile("cp.async.commit_group;" ::: "memory");
    };

    auto compute_stage = [&](int s) {
        const uint32_t sah = sbase + s * STG_BYTES;
        const uint32_t sal = sah + 16384;
        const uint32_t sbh = sah + 32768;
        const uint32_t sbl = sah + 40960;
        #pragma unroll
        for (int ks = 0; ks < 4; ++ks) {
            const int ach = ks * 2 + (lane >> 4);
            uint32_t rah[2][4], ral[2][4];
            #pragma unroll
            for (int mb = 0; mb < 2; ++mb) {
                const int row = wm + mb * 16 + (lane & 15);
                const uint32_t off = row * 128 + ((ach ^ (row & 7)) << 4);
                ldsm_x4(sah + off, rah[mb]);
                ldsm_x4(sal + off, ral[mb]);
            }
            uint32_t rbh[2][4], rbl[2][4];
            #pragma unroll
            for (int nb = 0; nb < 2; ++nb) {
                const int row = wn + nb * 16 + (lane & 15);
                const uint32_t off = row * 128 + ((ach ^ (row & 7)) << 4);
                ldsm_x4(sbh + off, rbh[nb]);
                ldsm_x4(sbl + off, rbl[nb]);
            }
            #pragma unroll
            for (int mb = 0; mb < 2; ++mb)
                #pragma unroll
                for (int nb = 0; nb < 2; ++nb) {
                    mma_bf16(acc[mb][nb * 2],     rah[mb], rbh[nb][0], rbh[nb][2]);
                    mma_bf16(acc[mb][nb * 2 + 1], rah[mb], rbh[nb][1], rbh[nb][3]);
                    mma_bf16(acc[mb][nb * 2],     ral[mb], rbh[nb][0], rbh[nb][2]);
                    mma_bf16(acc[mb][nb * 2 + 1], ral[mb], rbh[nb][1], rbh[nb][3]);
                    mma_bf16(acc[mb][nb * 2],     rah[mb], rbl[nb][0], rbl[nb][2]);
                    mma_bf16(acc[mb][nb * 2 + 1], rah[mb], rbl[nb][1], rbl[nb][3]);
                }
        }
    };

    const int NG = NGROUPS * KCPP;
    load_stage(0, 0);
    for (int g = 0; g < NG; ++g) {
        if (g + 1 < NG) {
            load_stage(g + 1, (g + 1) & 1);
            asm volatile("cp.async.wait_group 1;" ::: "memory");
        } else {
            asm volatile("cp.async.wait_group 0;" ::: "memory");
        }
        __syncthreads();
        compute_stage(g & 1);
        __syncthreads();
    }

    // ---- epilogue ----
    float sb[4][8];
    if (RANK8) {
        #pragma unroll
        for (int r = 0; r < 4; ++r) {
            const int gm = bm + wm + (r >> 1) * 16 + (lane >> 2) + (r & 1) * 8;
            if (gm < M) {
                *(float4*)&sb[r][0] = *(const float4*)&sbond8[gm * 8];
                *(float4*)&sb[r][4] = *(const float4*)&sbond8[gm * 8 + 4];
            }
        }
    }
    #pragma unroll
    for (int nb = 0; nb < 4; ++nb) {
        const int gn = bn + wn + nb * 8 + (lane & 3) * 2;
        float w0[8], w1[8];
        if (RANK8) {
            *(float4*)&w0[0] = *(const float4*)&wc8[gn * 8];
            *(float4*)&w0[4] = *(const float4*)&wc8[gn * 8 + 4];
            *(float4*)&w1[0] = *(const float4*)&wc8[(gn + 1) * 8];
            *(float4*)&w1[4] = *(const float4*)&wc8[(gn + 1) * 8 + 4];
        }
        #pragma unroll
        for (int mb = 0; mb < 2; ++mb)
            #pragma unroll
            for (int h = 0; h < 2; ++h) {
                const int gm = bm + wm + mb * 16 + (lane >> 2) + h * 8;
                if (gm < M) {
                    const int r = mb * 2 + h;
                    float vx = acc[mb][nb][h * 2];
                    float vy = acc[mb][nb][h * 2 + 1];
                    if (RANK8) {
                        vx += dot8(sb[r], w0);
                        vy += dot8(sb[r], w1);
                    }
                    if (SPLIT) {
                        __nv_bfloat162 lo2;
                        const __nv_bfloat162 hi2 = split_hi2(vx, vy, lo2);
                        *(__nv_bfloat162*)&Chi[(long)gm * LDC + gn] = hi2;
                        *(__nv_bfloat162*)&Clo[(long)gm * LDC + gn] = lo2;
                    } else {
                        *(float2*)&C[(long)gm * LDC + gn] = make_float2(vx, vy);
                    }
                }
            }
    }
}

// ======================= small kernels ======================================
__global__ void gather_split_kernel(const __nv_bfloat16* __restrict__ Ahi,
                                    const __nv_bfloat16* __restrict__ Alo,
                                    const int* __restrict__ aidx,
                                    const int* __restrict__ num_nbs,
                                    __nv_bfloat16* __restrict__ Ghi,
                                    __nv_bfloat16* __restrict__ Glo) {
    const int node = blockIdx.x;
    const int base = (node / NDIM) * NDIM;
    const int e0 = threadIdx.x * 4;
    const int nn = num_nbs[node];
    float s0 = 0.f, s1 = 0.f, s2 = 0.f, s3 = 0.f;
    #pragma unroll
    for (int k = 0; k < KNEI; ++k) {
        if (k >= nn) break;
        const int idx = __ldg(&aidx[((long)node * KNEI + k) * 2]);
        const long ro = (long)(base + idx) * HDIM + e0;
        const __nv_bfloat162 h0 = *(const __nv_bfloat162*)&Ahi[ro];
        const __nv_bfloat162 h1 = *(const __nv_bfloat162*)&Ahi[ro + 2];
        const __nv_bfloat162 l0 = *(const __nv_bfloat162*)&Alo[ro];
        const __nv_bfloat162 l1 = *(const __nv_bfloat162*)&Alo[ro + 2];
        s0 += __low2float(h0)  + __low2float(l0);
        s1 += __high2float(h0) + __high2float(l0);
        s2 += __low2float(h1)  + __low2float(l1);
        s3 += __high2float(h1) + __high2float(l1);
    }
    const long wo = (long)node * HDIM + e0;
    __nv_bfloat162 lo2a, lo2b;
    const __nv_bfloat162 hi2a = split_hi2(s0, s1, lo2a);
    const __nv_bfloat162 hi2b = split_hi2(s2, s3, lo2b);
    *(__nv_bfloat162*)&Ghi[wo]     = hi2a;
    *(__nv_bfloat162*)&Ghi[wo + 2] = hi2b;
    *(__nv_bfloat162*)&Glo[wo]     = lo2a;
    *(__nv_bfloat162*)&Glo[wo + 2] = lo2b;
}

// fused: split-pad raw input row AND gather-sum of neighbor raw rows
__global__ void pgather_kernel(const float* __restrict__ P,
                               const int* __restrict__ aidx,
                               const int* __restrict__ num_nbs,
                               __nv_bfloat16* __restrict__ Phi,
                               __nv_bfloat16* __restrict__ Plo,
                               __nv_bfloat16* __restrict__ Ghi,
                               __nv_bfloat16* __restrict__ Glo) {
    const int node = blockIdx.x;
    const int base = (node / NDIM) * NDIM;
    const int c = threadIdx.x;            // 0..127
    const float v = (c < FA) ? __ldg(&P[(long)node * FA + c]) : 0.f;
    const __nv_bfloat16 vh = __float2bfloat16_rn(v);
    Phi[(long)node * FAP + c] = vh;
    Plo[(long)node * FAP + c] = __float2bfloat16_rn(v - __bfloat162float(vh));

    const int nn = num_nbs[node];
    float s = 0.f;
    #pragma unroll
    for (int k = 0; k < KNEI; ++k) {
        if (k >= nn) break;
        const int idx = __ldg(&aidx[((long)node * KNEI + k) * 2]);
        if (c < FA) s += __ldg(&P[(long)(base + idx) * FA + c]);
    }
    const __nv_bfloat16 sh = __float2bfloat16_rn(s);
    Ghi[(long)node * FAP + c] = sh;
    Glo[(long)node * FAP + c] = __float2bfloat16_rn(s - __bfloat162float(sh));
}

// sbond8[node] = {s0..s4, cnt, 1, 0}
__global__ void sbond_kernel(const float* __restrict__ input_bond,
                             const int* __restrict__ bidx,
                             const int* __restrict__ num_nbs,
                             float* __restrict__ sbond) {
    const int node = blockIdx.x * blockDim.x + threadIdx.x;
    if (node >= MN) return;
    const int base = (node / NDIM) * NDIM;
    const int nn = num_nbs[node];
    float s[FB] = {};
    for (int k = 0; k < nn; ++k) {
        const int idx = __ldg(&bidx[((long)node * KNEI + k) * 2]);
        const float* r = input_bond + (long)(base + idx) * FB;
        #pragma unroll
        for (int f = 0; f < FB; ++f) s[f] += __ldg(&r[f]);
    }
    *(float4*)&sbond[node * 8]     = make_float4(s[0], s[1], s[2], s[3]);
    *(float4*)&sbond[node * 8 + 4] = make_float4(s[4], (float)nn, 1.f, 0.f);
}

// wc8[h] = {Wc[h][0..4], bc[h], b_U1[h], 0};  Wc = W_U1b@W_U2b, bc = W_U1b@b_U2
// 512 blocks (one h) x 128 threads, block reduce.
__global__ void wc_kernel(const float* __restrict__ W_U1,
                          const float* __restrict__ W_U2,
                          const float* __restrict__ b_U2,
                          const float* __restrict__ b_U1,
                          float* __restrict__ Wc) {
    __shared__ float red[4][6];
    const int h = blockIdx.x;
    const int tid = threadIdx.x, wid = tid >> 5, lane = tid & 31;
    float acc[6] = {};
    #pragma unroll
    for (int j = 0; j < 4; ++j) {
        const int m = tid + 128 * j;
        const float u = __ldg(&W_U1[(long)h * LDU1 + HDIM + m]);
        #pragma unroll
        for (int f = 0; f < FB; ++f)
            acc[f] += u * __ldg(&W_U2[(long)m * LDU2 + HDIM + f]);
        acc[5] += u * __ldg(&b_U2[m]);
    }
    #pragma unroll
    for (int f = 0; f < 6; ++f)
        #pragma unroll
        for (int o = 16; o; o >>= 1)
            acc[f] += __shfl_xor_sync(0xFFFFFFFF, acc[f], o);
    if (lane == 0) {
        #pragma unroll
        for (int f = 0; f < 6; ++f) red[wid][f] = acc[f];
    }
    __syncthreads();
    if (tid == 0) {
        float r[6];
        #pragma unroll
        for (int f = 0; f < 6; ++f)
            r[f] = red[0][f] + red[1][f] + red[2][f] + red[3][f];
        *(float4*)&Wc[h * 8] = make_float4(r[0], r[1], r[2], r[3]);
        *(float4*)&Wc[h * 8 + 4] = make_float4(r[4], r[5], __ldg(&b_U1[h]), 0.f);
    }
}

// transpose W_U2[:, 0:512] (ld=517) -> Wt[j][m] = W_U2[m][j], emit bf16 hi/lo
__global__ void transpose_split_kernel(const float* __restrict__ W,
                                       __nv_bfloat16* __restrict__ Thi,
                                       __nv_bfloat16* __restrict__ Tlo) {
    __shared__ float t[32][33];
    const int bx = blockIdx.x * 32, by = blockIdx.y * 32;
    const int x = threadIdx.x, y = threadIdx.y;    // 32 x 8
    #pragma unroll
    for (int i = 0; i < 32; i += 8)
        t[y + i][x] = __ldg(&W[(long)(by + y + i) * LDU2 + bx + x]);
    __syncthreads();
    #pragma unroll
    for (int i = 0; i < 32; i += 8) {
        const float v = t[x][y + i];
        const __nv_bfloat16 h = __float2bfloat16_rn(v);
        const long o = (long)(bx + y + i) * HDIM + by + x;
        Thi[o] = h;
        Tlo[o] = __float2bfloat16_rn(v - __bfloat162float(h));
    }
}

// transpose W_atom [512,89] -> Wet[f][m] (ld 512, f<89; padding rows stay 0)
__global__ void transpose_we_kernel(const float* __restrict__ W,
                                    __nv_bfloat16* __restrict__ Thi,
                                    __nv_bfloat16* __restrict__ Tlo) {
    __shared__ float t[32][33];
    const int bm = blockIdx.x * 32, bf = blockIdx.y * 32;
    const int x = threadIdx.x, y = threadIdx.y;    // 32 x 8
    #pragma unroll
    for (int i = 0; i < 32; i += 8) {
        const int m = bm + y + i, f = bf + x;
        t[y + i][x] = (f < FA) ? __ldg(&W[(long)m * FA + f]) : 0.f;
    }
    __syncthreads();
    #pragma unroll
    for (int i = 0; i < 32; i += 8) {
        const int f = bf + y + i, m = bm + x;
        if (f < FA) {
            const float v = t[x][y + i];
            const __nv_bfloat16 h = __float2bfloat16_rn(v);
            const long o = (long)f * HDIM + m;
            Thi[o] = h;
            Tlo[o] = __float2bfloat16_rn(v - __bfloat162float(h));
        }
    }
}

// strided weight split: out[n*512 + k] = W[n*ldw + koff + k]
__global__ void split_w_kernel(const float* __restrict__ W, int ldw, int koff,
                               __nv_bfloat16* __restrict__ hi,
                               __nv_bfloat16* __restrict__ lo) {
    const int idx = blockIdx.x * blockDim.x + threadIdx.x;
    if (idx >= HDIM * HDIM) return;
    const int n = idx >> 9, k = idx & 511;
    const float v = __ldg(&W[(long)n * ldw + koff + k]);
    const __nv_bfloat16 h = __float2bfloat16_rn(v);
    hi[idx] = h;
    lo[idx] = __float2bfloat16_rn(v - __bfloat162float(h));
}

// ======================= host ===============================================
extern "C" void kernel_launch(void* const* d_in, const int* in_sizes, int n_in,
                              void* d_out, int out_size) {
    const float* input_atom = (const float*)d_in[0];
    const float* input_bond = (const float*)d_in[1];
    const int*   atom_nei   = (const int*)d_in[2];
    const int*   bond_nei   = (const int*)d_in[3];
    const int*   num_nbs    = (const int*)d_in[4];
    const float* W_atom     = (const float*)d_in[5];
    const float* W_U2       = (const float*)d_in[6];
    const float* b_U2       = (const float*)d_in[7];
    const float* W_U1       = (const float*)d_in[8];
    const float* b_U1       = (const float*)d_in[9];
    float* out = (float*)d_out;

    float *sbond, *Wc;
    cudaGetSymbolAddress((void**)&sbond, g_sbond);
    cudaGetSymbolAddress((void**)&Wc, g_Wc);
    __nv_bfloat16 *Ahi0, *Alo0, *Ahi1, *Alo1, *GGhi, *GGlo;
    __nv_bfloat16 *Wahi, *Walo, *Wbhi, *Wblo, *Wfhi, *Wflo, *Wthi, *Wtlo;
    __nv_bfloat16 *Pahi, *Palo, *Pghi, *Pglo;
    __nv_bfloat16 *Wc1hi, *Wc1lo, *Wfehi, *Wfelo, *Wethi, *Wetlo;
    cudaGetSymbolAddress((void**)&Ahi0, g_Ahi0); cudaGetSymbolAddress((void**)&Alo0, g_Alo0);
    cudaGetSymbolAddress((void**)&Ahi1, g_Ahi1); cudaGetSymbolAddress((void**)&Alo1, g_Alo1);
    cudaGetSymbolAddress((void**)&GGhi, g_GGhi); cudaGetSymbolAddress((void**)&GGlo, g_GGlo);
    cudaGetSymbolAddress((void**)&Wahi, g_Wahi); cudaGetSymbolAddress((void**)&Walo, g_Walo);
    cudaGetSymbolAddress((void**)&Wbhi, g_Wbhi); cudaGetSymbolAddress((void**)&Wblo, g_Wblo);
    cudaGetSymbolAddress((void**)&Wfhi, g_Wfhi); cudaGetSymbolAddress((void**)&Wflo, g_Wflo);
    cudaGetSymbolAddress((void**)&Wthi, g_Wthi); cudaGetSymbolAddress((void**)&Wtlo, g_Wtlo);
    cudaGetSymbolAddress((void**)&Pahi, g_Pahi); cudaGetSymbolAddress((void**)&Palo, g_Palo);
    cudaGetSymbolAddress((void**)&Pghi, g_Pghi); cudaGetSymbolAddress((void**)&Pglo, g_Pglo);
    cudaGetSymbolAddress((void**)&Wc1hi, g_Wc1hi); cudaGetSymbolAddress((void**)&Wc1lo, g_Wc1lo);
    cudaGetSymbolAddress((void**)&Wfehi, g_Wfehi); cudaGetSymbolAddress((void**)&Wfelo, g_Wfelo);
    cudaGetSymbolAddress((void**)&Wethi, g_Wethi); cudaGetSymbolAddress((void**)&Wetlo, g_Wetlo);

    cudaFuncSetAttribute((const void*)mma_gemm64<1, 8, 512, 512, false, true>,
                         cudaFuncAttributeMaxDynamicSharedMemorySize, SMEM_G);
    cudaFuncSetAttribute((const void*)mma_gemm64<1, 8, 512, 128, false, true>,
                         cudaFuncAttributeMaxDynamicSharedMemorySize, SMEM_G);
    cudaFuncSetAttribute((const void*)mma_gemm64<2, 2, 128, 512, true, true>,
                         cudaFuncAttributeMaxDynamicSharedMemorySize, SMEM_G);
    cudaFuncSetAttribute((const void*)mma_gemm64<2, 8, 512, 512, true, true>,
                         cudaFuncAttributeMaxDynamicSharedMemorySize, SMEM_G);
    cudaFuncSetAttribute((const void*)mma_gemm64<2, 8, 512, 512, true, false>,
                         cudaFuncAttributeMaxDynamicSharedMemorySize, SMEM_G);

    const dim3 thr(256);
    const dim3 grid_main(HDIM / 64, (MN + 127) / 128);    // 8 x 90 = 720
    const dim3 grid_sq(HDIM / 64, HDIM / 128);            // 8 x 4 = 32
    const dim3 grid_wcomb(FAP / 64, HDIM / 128);          // 2 x 4 = 8
    const int wblocks = (HDIM * HDIM + 255) / 256;

    // 1-4. Weight transposes/splits
    transpose_split_kernel<<<dim3(16, 16), dim3(32, 8)>>>(W_U2, Wthi, Wtlo);
    split_w_kernel<<<wblocks, 256>>>(W_U1, LDU1, HDIM, Wbhi, Wblo);
    split_w_kernel<<<wblocks, 256>>>(W_U1, LDU1, 0, Wahi, Walo);
    transpose_we_kernel<<<dim3(16, 3), dim3(32, 8)>>>(W_atom, Wethi, Wetlo);

    // 5. Fold: Wf(hi/lo) = W_U1b @ W_U2a
    {
        GemmArgs3 p{};
        p.ahi[0] = Wbhi; p.alo[0] = Wblo; p.bhi[0] = Wthi; p.blo[0] = Wtlo;
        mma_gemm64<1, 8, 512, 512, false, true><<<grid_sq, thr, SMEM_G>>>(
            p, nullptr, Wfhi, Wflo, nullptr, nullptr, HDIM);
    }
    // 6. Wc1 = W_U1a @ W_atom  -> [512,128] hi/lo (cols>=89 garbage, harmless)
    {
        GemmArgs3 p{};
        p.ahi[0] = Wahi; p.alo[0] = Walo; p.bhi[0] = Wethi; p.blo[0] = Wetlo;
        mma_gemm64<1, 8, 512, 128, false, true><<<grid_wcomb, thr, SMEM_G>>>(
            p, nullptr, Wc1hi, Wc1lo, nullptr, nullptr, HDIM);
    }
    // 7. Wfe = Wf @ W_atom -> [512,128] hi/lo
    {
        GemmArgs3 p{};
        p.ahi[0] = Wfhi; p.alo[0] = Wflo; p.bhi[0] = Wethi; p.blo[0] = Wetlo;
        mma_gemm64<1, 8, 512, 128, false, true><<<grid_wcomb, thr, SMEM_G>>>(
            p, nullptr, Wfehi, Wfelo, nullptr, nullptr, HDIM);
    }

    // 8-10. Raw-input split+gather; bond rank-8 precompute
    pgather_kernel<<<MN, FAP>>>(input_atom, atom_nei, num_nbs,
                                Pahi, Palo, Pghi, Pglo);
    sbond_kernel<<<(MN + 127) / 128, 128>>>(input_bond, bond_nei, num_nbs, sbond);
    wc_kernel<<<HDIM, 128>>>(W_U1, W_U2, b_U2, b_U1, Wc);

    // 11. depth-0: A = P@Wc1^T + Pg@Wfe^T + sbond8.wc8   (K=128 x 2 groups)
    {
        GemmArgs3 p{};
        p.ahi[0] = Pahi; p.alo[0] = Palo; p.bhi[0] = Wc1hi; p.blo[0] = Wc1lo;
        p.ahi[1] = Pghi; p.alo[1] = Pglo; p.bhi[1] = Wfehi; p.blo[1] = Wfelo;
        mma_gemm64<2, 2, 128, 512, true, true><<<grid_main, thr, SMEM_G>>>(
            p, nullptr, Ahi0, Alo0, sbond, Wc, MN);
    }

    // 12+. depths 1..2: GG = gather(A); A' = A@W_U1a^T + GG@Wf^T + sbond8.wc8
    __nv_bfloat16* srcHi = Ahi0;
    __nv_bfloat16* srcLo = Alo0;
    for (int d = 1; d < DEPTH; ++d) {
        gather_split_kernel<<<MN, 128>>>(srcHi, srcLo, atom_nei, num_nbs,
                                         GGhi, GGlo);
        GemmArgs3 p{};
        p.ahi[0] = srcHi; p.alo[0] = srcLo; p.bhi[0] = Wahi; p.blo[0] = Walo;
        p.ahi[1] = GGhi;  p.alo[1] = GGlo;  p.bhi[1] = Wfhi; p.blo[1] = Wflo;
        if (d == DEPTH - 1) {
            mma_gemm64<2, 8, 512, 512, true, false><<<grid_main, thr, SMEM_G>>>(
                p, out, nullptr, nullptr, sbond, Wc, MN);
        } else {
            __nv_bfloat16* dstHi = (srcHi == Ahi0) ? Ahi1 : Ahi0;
            __nv_bfloat16* dstLo = (srcLo == Alo0) ? Alo1 : Alo0;
            mma_gemm64<2, 8, 512, 512, true, true><<<grid_main, thr, SMEM_G>>>(
                p, nullptr, dstHi, dstLo, sbond, Wc, MN);
            srcHi = dstHi; srcLo = dstLo;
        }
    }
}

// round 10
// speedup vs baseline: 3.2377x; 1.6809x over previous
#include <cuda_runtime.h>
#include <cuda_bf16.h>
#include <cstdint>

// Problem constants (fixed by the dataset)
#define BDIM 76
#define NDIM 151
#define KNEI 10
#define HDIM 512
#define FB 5
#define FA 89
#define FAP 128                   // padded raw-input K
#define MN (BDIM * NDIM)          // 11476 nodes
#define LDU2 (HDIM + FB)          // 517
#define LDU1 (2 * HDIM)           // 1024

// ---------------- static device scratch (no allocation allowed) -------------
__device__ __align__(128) float g_sb[MN * 8], g_Ssb[MN * 8], g_SSsb[MN * 8];
__device__ __align__(128) float g_wc8[HDIM * 8], g_P1[HDIM * 8], g_P2[HDIM * 8];
__device__ __align__(128) float g_R0[HDIM * 8], g_R1[HDIM * 8], g_R2[HDIM * 8];
__device__ __align__(128) float g_Wf[HDIM * HDIM];
__device__ __align__(128) float g_SX[MN * FAP], g_SSX[MN * FAP];
__device__ __align__(128) float g_T[4][FAP * HDIM];     // T0..T3 in-major fp32

__device__ __align__(128) __nv_bfloat16 g_Xhi[MN * FAP],   g_Xlo[MN * FAP];
__device__ __align__(128) __nv_bfloat16 g_SXhi[MN * FAP],  g_SXlo[MN * FAP];
__device__ __align__(128) __nv_bfloat16 g_SSXhi[MN * FAP], g_SSXlo[MN * FAP];
__device__ __align__(128) __nv_bfloat16 g_S3Xhi[MN * FAP], g_S3Xlo[MN * FAP];
__device__ __align__(128) __nv_bfloat16 g_Wahi[HDIM * HDIM], g_Walo[HDIM * HDIM];
__device__ __align__(128) __nv_bfloat16 g_Wbhi[HDIM * HDIM], g_Wblo[HDIM * HDIM];
__device__ __align__(128) __nv_bfloat16 g_Wthi[HDIM * HDIM], g_Wtlo[HDIM * HDIM];
__device__ __align__(128) __nv_bfloat16 g_Wfhi[HDIM * HDIM], g_Wflo[HDIM * HDIM];
__device__ __align__(128) __nv_bfloat16 g_Wethi[FAP * HDIM], g_Wetlo[FAP * HDIM];
// chain intermediates, in-major [128,512]
__device__ __align__(128) __nv_bfloat16 g_Uhi[FAP * HDIM],   g_Ulo[FAP * HDIM];
__device__ __align__(128) __nv_bfloat16 g_Vhi[FAP * HDIM],   g_Vlo[FAP * HDIM];
__device__ __align__(128) __nv_bfloat16 g_U20hi[FAP * HDIM], g_U20lo[FAP * HDIM];
__device__ __align__(128) __nv_bfloat16 g_U21hi[FAP * HDIM], g_U21lo[FAP * HDIM];
__device__ __align__(128) __nv_bfloat16 g_U22hi[FAP * HDIM], g_U22lo[FAP * HDIM];
// transposed T weights, B-format [512,128]
__device__ __align__(128) __nv_bfloat16 g_Tthi[4][HDIM * FAP], g_Ttlo[4][HDIM * FAP];

// ======================= PTX helpers (sm_80-safe only) ======================
__device__ __forceinline__ uint32_t smem_u32(const void* p) {
    uint32_t a;
    asm("{ .reg .u64 t; cvta.to.shared.u64 t, %1; cvt.u32.u64 %0, t; }"
        : "=r"(a) : "l"(p));
    return a;
}
__device__ __forceinline__ void cp_async16(uint32_t dst, const void* src, int sz) {
    asm volatile("cp.async.cg.shared.global [%0], [%1], 16, %2;"
                 :: "r"(dst), "l"(src), "r"(sz) : "memory");
}
__device__ __forceinline__ void ldsm_x4(uint32_t addr, uint32_t* r) {
    asm volatile("ldmatrix.sync.aligned.m8n8.x4.shared.b16 {%0,%1,%2,%3}, [%4];"
                 : "=r"(r[0]), "=r"(r[1]), "=r"(r[2]), "=r"(r[3]) : "r"(addr));
}
__device__ __forceinline__ void mma_bf16(float* c, const uint32_t* a,
                                         uint32_t b0, uint32_t b1) {
    asm volatile(
        "mma.sync.aligned.m16n8k16.row.col.f32.bf16.bf16.f32 "
        "{%0,%1,%2,%3}, {%4,%5,%6,%7}, {%8,%9}, {%0,%1,%2,%3};"
        : "+f"(c[0]), "+f"(c[1]), "+f"(c[2]), "+f"(c[3])
        : "r"(a[0]), "r"(a[1]), "r"(a[2]), "r"(a[3]), "r"(b0), "r"(b1));
}
__device__ __forceinline__ __nv_bfloat162 split_hi2(float x, float y,
                                                    __nv_bfloat162& lo2) {
    const __nv_bfloat16 hx = __float2bfloat16_rn(x);
    const __nv_bfloat16 hy = __float2bfloat16_rn(y);
    lo2 = __nv_bfloat162(__float2bfloat16_rn(x - __bfloat162float(hx)),
                         __float2bfloat16_rn(y - __bfloat162float(hy)));
    return __nv_bfloat162(hx, hy);
}
__device__ __forceinline__ float dot8(const float* s, const float* w) {
    return s[0]*w[0] + s[1]*w[1] + s[2]*w[2] + s[3]*w[3]
         + s[4]*w[4] + s[5]*w[5] + s[6]*w[6] + s[7]*w[7];
}

// ============ fused bf16x3 mma GEMM, 128x64 tiles, 2 CTAs/SM ================
// Per z (blockIdx.z) and group g: C += Ahi@Bhi^T + Alo@Bhi^T + Ahi@Blo^T
// Stage = {Ahi(16K), Alo(16K), Bhi(8K), Blo(8K)} of one 64-K chunk = 48KB.
// OUT: 0 = fp32 C, 1 = bf16 hi/lo split, 2 = both.
// RANK24: C += sb.R0 + Ssb.R1 + SSsb.R2 (three rank-8 dots), fused CONST.
#define STG_BYTES 49152
#define SMEM_G (2 * STG_BYTES)

struct Grp { const __nv_bfloat16 *ahi, *alo, *bhi, *blo; };
struct BatchArgs {
    Grp g[4][4];                       // [z][group]
    int ng[4];
    float* outC[4];
    __nv_bfloat16 *outHi[4], *outLo[4];
};

template <int KCPP, int LDA, int LDC, int OUT, bool RANK24>
__global__ __launch_bounds__(256, 2)
void mma_gemm64(const BatchArgs ba,
                const float* __restrict__ sb0, const float* __restrict__ sb1,
                const float* __restrict__ sb2,
                const float* __restrict__ R0, const float* __restrict__ R1,
                const float* __restrict__ R2, int M) {
    extern __shared__ __align__(128) char smem[];
    const uint32_t sbase = smem_u32(smem);
    const int z = blockIdx.z;
    const Grp* G = ba.g[z];
    const int tid = threadIdx.x, wid = tid >> 5, lane = tid & 31;
    const int bm = blockIdx.y * 128, bn = blockIdx.x * 64;
    const int wm = (wid & 3) * 32;
    const int wn = (wid >> 2) * 32;

    float acc[2][4][4] = {};

    const int lrow0 = tid >> 3;
    const int lch = tid & 7;
    auto load_stage = [&](int g, int s) {
        const int grp = g / KCPP, kc = g % KCPP;
        const uint32_t sbs = sbase + s * STG_BYTES;
        const __nv_bfloat16* TA[2] = { G[grp].ahi, G[grp].alo };
        #pragma unroll
        for (int t = 0; t < 2; ++t) {
            const uint32_t tb = sbs + t * 16384;
            #pragma unroll
            for (int it = 0; it < 4; ++it) {
                const int row = lrow0 + it * 32;
                const uint32_t soff = row * 128 + ((lch ^ (row & 7)) << 4);
                const long gr = bm + row;
                cp_async16(tb + soff, TA[t] + gr * LDA + kc * 64 + lch * 8,
                           (gr < M) ? 16 : 0);
            }
        }
        const __nv_bfloat16* TB[2] = { G[grp].bhi, G[grp].blo };
        #pragma unroll
        for (int t = 0; t < 2; ++t) {
            const uint32_t tb = sbs + 32768 + t * 8192;
            #pragma unroll
            for (int it = 0; it < 2; ++it) {
                const int row = lrow0 + it * 32;
                const uint32_t soff = row * 128 + ((lch ^ (row & 7)) << 4);
                const long gr = bn + row;
                cp_async16(tb + soff, TB[t] + gr * LDA + kc * 64 + lch * 8, 16);
            }
        }
        asm volatile("cp.async.commit_group;" ::: "memory");
    };

    auto compute_stage = [&](int s) {
        const uint32_t sah = sbase + s * STG_BYTES;
        const uint32_t sal = sah + 16384;
        const uint32_t sbh = sah + 32768;
        const uint32_t sbl = sah + 40960;
        #pragma unroll
        for (int ks = 0; ks < 4; ++ks) {
            const int ach = ks * 2 + (lane >> 4);
            uint32_t rah[2][4], ral[2][4];
            #pragma unroll
            for (int mb = 0; mb < 2; ++mb) {
                const int row = wm + mb * 16 + (lane & 15);
                const uint32_t off = row * 128 + ((ach ^ (row & 7)) << 4);
                ldsm_x4(sah + off, rah[mb]);
                ldsm_x4(sal + off, ral[mb]);
            }
            uint32_t rbh[2][4], rbl[2][4];
            #pragma unroll
            for (int nb = 0; nb < 2; ++nb) {
                const int row = wn + nb * 16 + (lane & 15);
                const uint32_t off = row * 128 + ((ach ^ (row & 7)) << 4);
                ldsm_x4(sbh + off, rbh[nb]);
                ldsm_x4(sbl + off, rbl[nb]);
            }
            #pragma unroll
            for (int mb = 0; mb < 2; ++mb)
                #pragma unroll
                for (int nb = 0; nb < 2; ++nb) {
                    mma_bf16(acc[mb][nb * 2],     rah[mb], rbh[nb][0], rbh[nb][2]);
                    mma_bf16(acc[mb][nb * 2 + 1], rah[mb], rbh[nb][1], rbh[nb][3]);
                    mma_bf16(acc[mb][nb * 2],     ral[mb], rbh[nb][0], rbh[nb][2]);
                    mma_bf16(acc[mb][nb * 2 + 1], ral[mb], rbh[nb][1], rbh[nb][3]);
                    mma_bf16(acc[mb][nb * 2],     rah[mb], rbl[nb][0], rbl[nb][2]);
                    mma_bf16(acc[mb][nb * 2 + 1], rah[mb], rbl[nb][1], rbl[nb][3]);
                }
        }
    };

    const int NG = ba.ng[z] * KCPP;
    load_stage(0, 0);
    for (int g = 0; g < NG; ++g) {
        if (g + 1 < NG) {
            load_stage(g + 1, (g + 1) & 1);
            asm volatile("cp.async.wait_group 1;" ::: "memory");
        } else {
            asm volatile("cp.async.wait_group 0;" ::: "memory");
        }
        __syncthreads();
        compute_stage(g & 1);
        __syncthreads();
    }

    // ---- rank-24 additive term (before store) ----
    if (RANK24) {
        #pragma unroll
        for (int t = 0; t < 3; ++t) {
            const float* sbp = (t == 0) ? sb0 : (t == 1) ? sb1 : sb2;
            const float* Rp  = (t == 0) ? R0  : (t == 1) ? R1  : R2;
            float sv[4][8];
            #pragma unroll
            for (int r = 0; r < 4; ++r) {
                const int gm = bm + wm + (r >> 1) * 16 + (lane >> 2) + (r & 1) * 8;
                if (gm < M) {
                    *(float4*)&sv[r][0] = *(const float4*)&sbp[gm * 8];
                    *(float4*)&sv[r][4] = *(const float4*)&sbp[gm * 8 + 4];
                } else {
                    #pragma unroll
                    for (int j = 0; j < 8; ++j) sv[r][j] = 0.f;
                }
            }
            #pragma unroll
            for (int nb = 0; nb < 4; ++nb) {
                const int gn = bn + wn + nb * 8 + (lane & 3) * 2;
                float w0[8], w1[8];
                *(float4*)&w0[0] = *(const float4*)&Rp[gn * 8];
                *(float4*)&w0[4] = *(const float4*)&Rp[gn * 8 + 4];
                *(float4*)&w1[0] = *(const float4*)&Rp[(gn + 1) * 8];
                *(float4*)&w1[4] = *(const float4*)&Rp[(gn + 1) * 8 + 4];
                #pragma unroll
                for (int mb = 0; mb < 2; ++mb)
                    #pragma unroll
                    for (int h = 0; h < 2; ++h) {
                        const int r = mb * 2 + h;
                        acc[mb][nb][h * 2]     += dot8(sv[r], w0);
                        acc[mb][nb][h * 2 + 1] += dot8(sv[r], w1);
                    }
            }
        }
    }

    // ---- store ----
    float* C = ba.outC[z];
    __nv_bfloat16* Chi = ba.outHi[z];
    __nv_bfloat16* Clo = ba.outLo[z];
    #pragma unroll
    for (int nb = 0; nb < 4; ++nb) {
        const int gn = bn + wn + nb * 8 + (lane & 3) * 2;
        #pragma unroll
        for (int mb = 0; mb < 2; ++mb)
            #pragma unroll
            for (int h = 0; h < 2; ++h) {
                const int gm = bm + wm + mb * 16 + (lane >> 2) + h * 8;
                if (gm < M) {
                    const float vx = acc[mb][nb][h * 2];
                    const float vy = acc[mb][nb][h * 2 + 1];
                    if (OUT == 0 || OUT == 2)
                        *(float2*)&C[(long)gm * LDC + gn] = make_float2(vx, vy);
                    if (OUT == 1 || OUT == 2) {
                        __nv_bfloat162 lo2;
                        const __nv_bfloat162 hi2 = split_hi2(vx, vy, lo2);
                        *(__nv_bfloat162*)&Chi[(long)gm * LDC + gn] = hi2;
                        *(__nv_bfloat162*)&Clo[(long)gm * LDC + gn] = lo2;
                    }
                }
            }
    }
}

// ================= fused prep0: weight splits/transposes + wc8 ==============
// blocks [0,1024): split W_U1a -> Wa hi/lo
// blocks [1024,2048): split W_U1b -> Wb hi/lo
// blocks [2048,2304): transpose W_U2a (ld 517) -> Wt hi/lo
// blocks [2304,2352): transpose W_atom -> Wet hi/lo ([128,512], pad rows stay 0)
// blocks [2352,2864): wc8[h] = {W_U1b@W_U2b (5), W_U1b@b_U2, b_U1[h], 0}
__global__ __launch_bounds__(256)
void prep0_kernel(const float* __restrict__ W_U1,
                  const float* __restrict__ W_U2,
                  const float* __restrict__ W_atom,
                  const float* __restrict__ b_U2,
                  const float* __restrict__ b_U1) {
    __shared__ float sh[32 * 33];
    const int b = blockIdx.x, tid = threadIdx.x;
    if (b < 2048) {
        const int koff = (b < 1024) ? 0 : HDIM;
        __nv_bfloat16* hi = (b < 1024) ? g_Wahi : g_Wbhi;
        __nv_bfloat16* lo = (b < 1024) ? g_Walo : g_Wblo;
        const int idx = (b & 1023) * 256 + tid;
        const int n = idx >> 9, k = idx & 511;
        const float v = __ldg(&W_U1[(long)n * LDU1 + koff + k]);
        const __nv_bfloat16 h = __float2bfloat16_rn(v);
        hi[idx] = h;
        lo[idx] = __float2bfloat16_rn(v - __bfloat162float(h));
    } else if (b < 2304) {
        const int bb = b - 2048;
        const int bx = (bb & 15) * 32, by = (bb >> 4) * 32;
        const int x = tid & 31, y = tid >> 5;        // 32 x 8
        #pragma unroll
        for (int i = 0; i < 32; i += 8)
            sh[(y + i) * 33 + x] = __ldg(&W_U2[(long)(by + y + i) * LDU2 + bx + x]);
        __syncthreads();
        #pragma unroll
        for (int i = 0; i < 32; i += 8) {
            const float v = sh[x * 33 + y + i];
            const __nv_bfloat16 h = __float2bfloat16_rn(v);
            const long o = (long)(bx + y + i) * HDIM + by + x;
            g_Wthi[o] = h;
            g_Wtlo[o] = __float2bfloat16_rn(v - __bfloat162float(h));
        }
    } else if (b < 2352) {
        const int bb = b - 2304;
        const int bm = (bb % 16) * 32, bf = (bb / 16) * 32;
        const int x = tid & 31, y = tid >> 5;
        #pragma unroll
        for (int i = 0; i < 32; i += 8) {
            const int m = bm + y + i, f = bf + x;
            sh[(y + i) * 33 + x] = (f < FA) ? __ldg(&W_atom[(long)m * FA + f]) : 0.f;
        }
        __syncthreads();
        #pragma unroll
        for (int i = 0; i < 32; i += 8) {
            const int f = bf + y + i, m = bm + x;
            if (f < FA) {
                const float v = sh[x * 33 + y + i];
                const __nv_bfloat16 h = __float2bfloat16_rn(v);
                const long o = (long)f * HDIM + m;
                g_Wethi[o] = h;
                g_Wetlo[o] = __float2bfloat16_rn(v - __bfloat162float(h));
            }
        }
    } else {
        const int h = b - 2352;
        const int w = tid >> 5, lane = tid & 31;
        float acc[6] = {};
        #pragma unroll
        for (int j = 0; j < 2; ++j) {
            const int m = tid + 256 * j;
            const float u = __ldg(&W_U1[(long)h * LDU1 + HDIM + m]);
            #pragma unroll
            for (int f = 0; f < FB; ++f)
                acc[f] += u * __ldg(&W_U2[(long)m * LDU2 + HDIM + f]);
            acc[5] += u * __ldg(&b_U2[m]);
        }
        #pragma unroll
        for (int f = 0; f < 6; ++f)
            #pragma unroll
            for (int o = 16; o; o >>= 1)
                acc[f] += __shfl_xor_sync(0xFFFFFFFF, acc[f], o);
        if (lane == 0)
            #pragma unroll
            for (int f = 0; f < 6; ++f) sh[w * 8 + f] = acc[f];
        __syncthreads();
        if (tid == 0) {
            float r[6];
            #pragma unroll
            for (int f = 0; f < 6; ++f) {
                r[f] = 0.f;
                #pragma unroll
                for (int ww = 0; ww < 8; ++ww) r[f] += sh[ww * 8 + f];
            }
            *(float4*)&g_wc8[h * 8] = make_float4(r[0], r[1], r[2], r[3]);
            *(float4*)&g_wc8[h * 8 + 4] = make_float4(r[4], r[5],
                                                      __ldg(&b_U1[h]), 0.f);
        }
    }
}

// ========== transpose T0..T3 [128,512] fp32 -> B-format [512,128] hi/lo =====
__global__ __launch_bounds__(256)
void transpose_T_kernel() {
    __shared__ float sh[32 * 33];
    const int zi = blockIdx.z;
    const float* in = g_T[zi];
    __nv_bfloat16* ohi = g_Tthi[zi];
    __nv_bfloat16* olo = g_Ttlo[zi];
    const int bn = blockIdx.x * 32, bk = blockIdx.y * 32;
    const int x = threadIdx.x & 31, y = threadIdx.x >> 5;
    #pragma unroll
    for (int i = 0; i < 32; i += 8)
        sh[(y + i) * 33 + x] = __ldg(&in[(long)(bk + y + i) * HDIM + bn + x]);
    __syncthreads();
    #pragma unroll
    for (int i = 0; i < 32; i += 8) {
        const float v = sh[x * 33 + y + i];
        const __nv_bfloat16 h = __float2bfloat16_rn(v);
        const long o = (long)(bn + y + i) * FAP + bk + x;
        ohi[o] = h;
        olo[o] = __float2bfloat16_rn(v - __bfloat162float(h));
    }
}

// ================= rank-24 fold kernels =====================================
// P1[n,j] = sum_m W_U1a[n,m]*wc8[m,j];  P2 with Wf.
__global__ __launch_bounds__(64)
void rankA_kernel(const float* __restrict__ W_U1) {
    const int n = blockIdx.x;
    const int w = threadIdx.x >> 5, lane = threadIdx.x & 31;
    float acc[8] = {};
    for (int m = lane; m < HDIM; m += 32) {
        const float u = (w == 0) ? __ldg(&W_U1[(long)n * LDU1 + m])
                                 : g_Wf[(long)n * HDIM + m];
        #pragma unroll
        for (int j = 0; j < 8; ++j) acc[j] += u * g_wc8[m * 8 + j];
    }
    #pragma unroll
    for (int j = 0; j < 8; ++j)
        #pragma unroll
        for (int o = 16; o; o >>= 1)
            acc[j] += __shfl_xor_sync(0xFFFFFFFF, acc[j], o);
    if (lane == 0) {
        float* dst = (w == 0) ? g_P1 : g_P2;
        #pragma unroll
        for (int j = 0; j < 8; ++j) dst[n * 8 + j] = acc[j];
    }
}

// Q-products and final R vectors:
// R0 = Wa o (P1+wc8) + wc8;  R1 = Wa o P2 + Wf o (P1+wc8);  R2 = Wf o P2
__global__ __launch_bounds__(128)
void rankB_kernel(const float* __restrict__ W_U1) {
    __shared__ float sm[4][8];
    const int n = blockIdx.x;
    const int w = threadIdx.x >> 5, lane = threadIdx.x & 31;
    const bool useWa = (w == 0 || w == 2);
    const bool usePw = (w < 2);
    float acc[8] = {};
    for (int m = lane; m < HDIM; m += 32) {
        const float u = useWa ? __ldg(&W_U1[(long)n * LDU1 + m])
                              : g_Wf[(long)n * HDIM + m];
        #pragma unroll
        for (int j = 0; j < 8; ++j) {
            const float rv = usePw ? (g_P1[m * 8 + j] + g_wc8[m * 8 + j])
                                   : g_P2[m * 8 + j];
            acc[j] += u * rv;
        }
    }
    #pragma unroll
    for (int j = 0; j < 8; ++j)
        #pragma unroll
        for (int o = 16; o; o >>= 1)
            acc[j] += __shfl_xor_sync(0xFFFFFFFF, acc[j], o);
    if (lane == 0)
        #pragma unroll
        for (int j = 0; j < 8; ++j) sm[w][j] = acc[j];
    __syncthreads();
    if (threadIdx.x == 0) {
        #pragma unroll
        for (int j = 0; j < 8; ++j) {
            g_R0[n * 8 + j] = sm[0][j] + g_wc8[n * 8 + j];  // QA1 + wc8
            g_R1[n * 8 + j] = sm[2][j] + sm[1][j];          // QA2 + QF1
            g_R2[n * 8 + j] = sm[3][j];                     // QF2
        }
    }
}

// ================= runtime gather kernels ===================================
// pgather: X pad-split, SX = gather(X) fp32+split, sb (threads 0..7)
__global__ __launch_bounds__(FAP)
void pgather_kernel(const float* __restrict__ P,
                    const float* __restrict__ input_bond,
                    const int* __restrict__ aidx,
                    const int* __restrict__ bidx,
                    const int* __restrict__ num_nbs) {
    const int node = blockIdx.x;
    const int base = (node / NDIM) * NDIM;
    const int c = threadIdx.x;
    const int nn = num_nbs[node];
    const float v = (c < FA) ? __ldg(&P[(long)node * FA + c]) : 0.f;
    const __nv_bfloat16 vh = __float2bfloat16_rn(v);
    g_Xhi[(long)node * FAP + c] = vh;
    g_Xlo[(long)node * FAP + c] = __float2bfloat16_rn(v - __bfloat162float(vh));

    float s = 0.f;
    if (c < FA) {
        #pragma unroll
        for (int k = 0; k < KNEI; ++k) {
            if (k >= nn) break;
            const int idx = __ldg(&aidx[((long)node * KNEI + k) * 2]);
            s += __ldg(&P[(long)(base + idx) * FA + c]);
        }
    }
    g_SX[(long)node * FAP + c] = s;
    const __nv_bfloat16 sh = __float2bfloat16_rn(s);
    g_SXhi[(long)node * FAP + c] = sh;
    g_SXlo[(long)node * FAP + c] = __float2bfloat16_rn(s - __bfloat162float(sh));

    if (c < 8) {
        float sv;
        if (c < FB) {
            sv = 0.f;
            for (int k = 0; k < nn; ++k) {
                const int idx = __ldg(&bidx[((long)node * KNEI + k) * 2]);
                sv += __ldg(&input_bond[(long)(base + idx) * FB + c]);
            }
        } else sv = (c == 5) ? (float)nn : (c == 6) ? 1.f : 0.f;
        g_sb[node * 8 + c] = sv;
    }
}

// generic K=128 gather: out = gather(in fp32); optional fp32 out; hi/lo split.
// threads 0..7 also gather sbin -> sbout.
template <bool WF32>
__global__ __launch_bounds__(FAP)
void gatherK_kernel(const float* __restrict__ in, float* __restrict__ outf,
                    __nv_bfloat16* __restrict__ ohi, __nv_bfloat16* __restrict__ olo,
                    const float* __restrict__ sbin, float* __restrict__ sbout,
                    const int* __restrict__ aidx, const int* __restrict__ num_nbs) {
    const int node = blockIdx.x;
    const int base = (node / NDIM) * NDIM;
    const int c = threadIdx.x;
    const int nn = num_nbs[node];
    float s = 0.f;
    float sb = 0.f;
    #pragma unroll
    for (int k = 0; k < KNEI; ++k) {
        if (k >= nn) break;
        const int idx = __ldg(&aidx[((long)node * KNEI + k) * 2]);
        s += __ldg(&in[(long)(base + idx) * FAP + c]);
        if (c < 8) sb += __ldg(&sbin[(base + idx) * 8 + c]);
    }
    if (WF32) outf[(long)node * FAP + c] = s;
    const __nv_bfloat16 sh = __float2bfloat16_rn(s);
    ohi[(long)node * FAP + c] = sh;
    olo[(long)node * FAP + c] = __float2bfloat16_rn(s - __bfloat162float(sh));
    if (c < 8) sbout[node * 8 + c] = sb;
}

// ======================= host ===============================================
extern "C" void kernel_launch(void* const* d_in, const int* in_sizes, int n_in,
                              void* d_out, int out_size) {
    const float* input_atom = (const float*)d_in[0];
    const float* input_bond = (const float*)d_in[1];
    const int*   atom_nei   = (const int*)d_in[2];
    const int*   bond_nei   = (const int*)d_in[3];
    const int*   num_nbs    = (const int*)d_in[4];
    const float* W_atom     = (const float*)d_in[5];
    const float* W_U2       = (const float*)d_in[6];
    const float* b_U2       = (const float*)d_in[7];
    const float* W_U1       = (const float*)d_in[8];
    const float* b_U1       = (const float*)d_in[9];
    float* out = (float*)d_out;

    // symbol addresses
    #define GA(p, s) cudaGetSymbolAddress((void**)&p, s)
    float *sb, *Ssb, *SSsb, *R0, *R1, *R2, *Wf, *SX, *SSX;
    GA(sb, g_sb); GA(Ssb, g_Ssb); GA(SSsb, g_SSsb);
    GA(R0, g_R0); GA(R1, g_R1); GA(R2, g_R2);
    GA(Wf, g_Wf); GA(SX, g_SX); GA(SSX, g_SSX);
    float (*T)[FAP * HDIM]; GA(T, g_T);
    __nv_bfloat16 *Xhi, *Xlo, *SXhi, *SXlo, *SSXhi, *SSXlo, *S3Xhi, *S3Xlo;
    GA(Xhi, g_Xhi); GA(Xlo, g_Xlo); GA(SXhi, g_SXhi); GA(SXlo, g_SXlo);
    GA(SSXhi, g_SSXhi); GA(SSXlo, g_SSXlo); GA(S3Xhi, g_S3Xhi); GA(S3Xlo, g_S3Xlo);
    __nv_bfloat16 *Wahi, *Walo, *Wbhi, *Wblo, *Wthi, *Wtlo, *Wfhi, *Wflo;
    __nv_bfloat16 *Wethi, *Wetlo;
    GA(Wahi, g_Wahi); GA(Walo, g_Walo); GA(Wbhi, g_Wbhi); GA(Wblo, g_Wblo);
    GA(Wthi, g_Wthi); GA(Wtlo, g_Wtlo); GA(Wfhi, g_Wfhi); GA(Wflo, g_Wflo);
    GA(Wethi, g_Wethi); GA(Wetlo, g_Wetlo);
    __nv_bfloat16 *Uhi, *Ulo, *Vhi, *Vlo;
    __nv_bfloat16 *U20hi, *U20lo, *U21hi, *U21lo, *U22hi, *U22lo;
    GA(Uhi, g_Uhi); GA(Ulo, g_Ulo); GA(Vhi, g_Vhi); GA(Vlo, g_Vlo);
    GA(U20hi, g_U20hi); GA(U20lo, g_U20lo); GA(U21hi, g_U21hi);
    GA(U21lo, g_U21lo); GA(U22hi, g_U22hi); GA(U22lo, g_U22lo);
    __nv_bfloat16 (*Tthi)[HDIM * FAP], (*Ttlo)[HDIM * FAP];
    GA(Tthi, g_Tthi); GA(Ttlo, g_Ttlo);
    #undef GA

    cudaFuncSetAttribute((const void*)mma_gemm64<8, 512, 512, 2, false>,
                         cudaFuncAttributeMaxDynamicSharedMemorySize, SMEM_G);
    cudaFuncSetAttribute((const void*)mma_gemm64<8, 512, 512, 1, false>,
                         cudaFuncAttributeMaxDynamicSharedMemorySize, SMEM_G);
    cudaFuncSetAttribute((const void*)mma_gemm64<8, 512, 512, 0, false>,
                         cudaFuncAttributeMaxDynamicSharedMemorySize, SMEM_G);
    cudaFuncSetAttribute((const void*)mma_gemm64<2, 128, 512, 0, true>,
                         cudaFuncAttributeMaxDynamicSharedMemorySize, SMEM_G);

    const dim3 thr(256);

    // 1. fused prep
    prep0_kernel<<<2864, 256>>>(W_U1, W_U2, W_atom, b_U2, b_U1);

    // 2. Wf = W_U1b @ W_U2a  (fp32 + hi/lo), M=512
    {
        BatchArgs ba{};
        ba.g[0][0] = { Wbhi, Wblo, Wthi, Wtlo };
        ba.ng[0] = 1; ba.outC[0] = Wf; ba.outHi[0] = Wfhi; ba.outLo[0] = Wflo;
        mma_gemm64<8, 512, 512, 2, false><<<dim3(8, 4, 1), thr, SMEM_G>>>(
            ba, nullptr, nullptr, nullptr, nullptr, nullptr, nullptr, HDIM);
    }
    // 3. {U, V} = Wet o {Wa, Wf}, M=128, split
    {
        BatchArgs ba{};
        ba.g[0][0] = { Wethi, Wetlo, Wahi, Walo };
        ba.g[1][0] = { Wethi, Wetlo, Wfhi, Wflo };
        ba.ng[0] = ba.ng[1] = 1;
        ba.outHi[0] = Uhi; ba.outLo[0] = Ulo;
        ba.outHi[1] = Vhi; ba.outLo[1] = Vlo;
        mma_gemm64<8, 512, 512, 1, false><<<dim3(8, 1, 2), thr, SMEM_G>>>(
            ba, nullptr, nullptr, nullptr, nullptr, nullptr, nullptr, FAP);
    }
    // 4. {U20, U21, U22}, M=128, split
    {
        BatchArgs ba{};
        ba.g[0][0] = { Uhi, Ulo, Wahi, Walo };                        ba.ng[0] = 1;
        ba.g[1][0] = { Vhi, Vlo, Wahi, Walo };
        ba.g[1][1] = { Uhi, Ulo, Wfhi, Wflo };                        ba.ng[1] = 2;
        ba.g[2][0] = { Vhi, Vlo, Wfhi, Wflo };                        ba.ng[2] = 1;
        ba.outHi[0] = U20hi; ba.outLo[0] = U20lo;
        ba.outHi[1] = U21hi; ba.outLo[1] = U21lo;
        ba.outHi[2] = U22hi; ba.outLo[2] = U22lo;
        mma_gemm64<8, 512, 512, 1, false><<<dim3(8, 1, 3), thr, SMEM_G>>>(
            ba, nullptr, nullptr, nullptr, nullptr, nullptr, nullptr, FAP);
    }
    // 5. {T0..T3}, M=128, fp32
    {
        BatchArgs ba{};
        ba.g[0][0] = { U20hi, U20lo, Wahi, Walo };                    ba.ng[0] = 1;
        ba.g[1][0] = { U21hi, U21lo, Wahi, Walo };
        ba.g[1][1] = { U20hi, U20lo, Wfhi, Wflo };                    ba.ng[1] = 2;
        ba.g[2][0] = { U22hi, U22lo, Wahi, Walo };
        ba.g[2][1] = { U21hi, U21lo, Wfhi, Wflo };                    ba.ng[2] = 2;
        ba.g[3][0] = { U22hi, U22lo, Wfhi, Wflo };                    ba.ng[3] = 1;
        ba.outC[0] = T[0]; ba.outC[1] = T[1]; ba.outC[2] = T[2]; ba.outC[3] = T[3];
        mma_gemm64<8, 512, 512, 0, false><<<dim3(8, 1, 4), thr, SMEM_G>>>(
            ba, nullptr, nullptr, nullptr, nullptr, nullptr, nullptr, FAP);
    }
    // 6. transpose T -> B-format hi/lo
    transpose_T_kernel<<<dim3(16, 4, 4), 256>>>();

    // 7-8. rank-24 folds
    rankA_kernel<<<HDIM, 64>>>(W_U1);
    rankB_kernel<<<HDIM, 128>>>(W_U1);

    // 9-11. runtime gathers
    pgather_kernel<<<MN, FAP>>>(input_atom, input_bond, atom_nei, bond_nei,
                                num_nbs);
    gatherK_kernel<true><<<MN, FAP>>>(SX, SSX, SSXhi, SSXlo, sb, Ssb,
                                      atom_nei, num_nbs);
    gatherK_kernel<false><<<MN, FAP>>>(SSX, nullptr, S3Xhi, S3Xlo, Ssb, SSsb,
                                       atom_nei, num_nbs);

    // 12. mega GEMM: out = X@T0 + SX@T1 + SSX@T2 + S3X@T3 + rank24
    {
        BatchArgs ba{};
        ba.g[0][0] = { Xhi,   Xlo,   Tthi[0], Ttlo[0] };
        ba.g[0][1] = { SXhi,  SXlo,  Tthi[1], Ttlo[1] };
        ba.g[0][2] = { SSXhi, SSXlo, Tthi[2], Ttlo[2] };
        ba.g[0][3] = { S3Xhi, S3Xlo, Tthi[3], Ttlo[3] };
        ba.ng[0] = 4;
        ba.outC[0] = out;
        mma_gemm64<2, 128, 512, 0, true><<<dim3(8, 90, 1), thr, SMEM_G>>>(
            ba, sb, Ssb, SSsb, R0, R1, R2, MN);
    }
}